// round 1
// baseline (speedup 1.0000x reference)
#include <cuda_runtime.h>
#include <math.h>

// ---------------- problem constants ----------------
#define BB 8
#define CC 640
#define HW 4096     // 64*64
#define KDIM 160
#define MR 4
#define GROUPS 32
#define CPG 20      // 640/32

// ---------------- scratch (device globals; no allocs allowed) ----------------
__device__ float g_t   [MR*CC*64];          // 8x8 conv1x1 result per memory row
__device__ float g_dec [MR*CC*HW];          // decoded refs per memory row
__device__ float g_wref[BB*CC*HW];          // weighted reference
__device__ float g_big [BB*2*CC*HW];        // rows 0..639: f1 ; rows 640..1279: gate-pre
__device__ float g_f2  [BB*CC*HW];          // after gn+gelu+dwconv
__device__ float g_qp  [BB*KDIM*64];        // q-pool partials (64 pixel-tiles)
__device__ float g_gn  [BB*GROUPS*2];       // mu, rsigma per (b,group)
__device__ float g_attnw[BB*2];
__device__ int   g_attni[BB*2];

__device__ __forceinline__ float gelu_f(float v){
    return 0.5f*v*(1.0f + erff(v*0.70710678118654752f));
}

// ---------------- generic tiled SGEMM ----------------
// Y[bz, o, p] = sum_c W[o,c] * X[bz,c,p] + bias[o]
// W rows split across (Wa,Wb) at rowSplit; X channels split across (Xa,Xb) at chanSplit.
// EPI: 0 = plain store, 1 = final (sigmoid-gate blend), 2 = q-projection (gelu + pixel reduce)
constexpr int GK = 16;

template<int TBM, int TBN, int EPI>
__global__ __launch_bounds__(256) void gemm_tpl(
    const float* __restrict__ Wa, const float* __restrict__ Wb, int rowSplit,
    const float* __restrict__ Xa, long long sXa,
    const float* __restrict__ Xb, long long sXb, int chanSplit,
    const float* __restrict__ biasa, const float* __restrict__ biasb,
    float* __restrict__ Y, long long sY,
    int M, int N, int K,
    const float* __restrict__ ep_g, long long s_g,
    const float* __restrict__ ep_x, long long s_x,
    float* __restrict__ ep_qp)
{
    constexpr int TM = TBM/16, TN = TBN/16;
    __shared__ float As[GK][TBM];
    __shared__ float Bs[GK][TBN];
    __shared__ float Red[TBM][17];

    const int tid = threadIdx.x;
    const int tx = tid & 15, ty = tid >> 4;
    const int pBase = blockIdx.x * TBN;
    const int oBase = blockIdx.y * TBM;
    const int bz = blockIdx.z;

    float acc[TM][TN];
#pragma unroll
    for (int i = 0; i < TM; i++)
#pragma unroll
        for (int j = 0; j < TN; j++) acc[i][j] = 0.f;

    for (int c0 = 0; c0 < K; c0 += GK){
        // load A tile (transposed into As[k][m])
#pragma unroll
        for (int l = 0; l < TBM/64; l++){
            int i = (tid >> 2) + l*64;
            int j4 = (tid & 3) << 2;
            int o = oBase + i;
            float4 w = make_float4(0.f,0.f,0.f,0.f);
            if (o < M){
                const float* wp = (o < rowSplit) ? (Wa + (long long)o*K)
                                                 : (Wb + (long long)(o-rowSplit)*K);
                w = *(const float4*)(wp + c0 + j4);
            }
            As[j4+0][i] = w.x; As[j4+1][i] = w.y; As[j4+2][i] = w.z; As[j4+3][i] = w.w;
        }
        // load B tile
#pragma unroll
        for (int l = 0; l < TBN/64; l++){
            int j = tid >> 4;
            int n4 = ((tid & 15) << 2) + l*64;
            int c = c0 + j;
            const float* xp = (c < chanSplit) ? (Xa + bz*sXa + (long long)c*N)
                                              : (Xb + bz*sXb + (long long)(c - chanSplit)*N);
            *(float4*)&Bs[j][n4] = *(const float4*)(xp + pBase + n4);
        }
        __syncthreads();
#pragma unroll
        for (int kk = 0; kk < GK; kk++){
            float a[TM], b[TN];
#pragma unroll
            for (int i = 0; i < TM; i += 4){
                float4 t = *(const float4*)&As[kk][ty*TM + i];
                a[i]=t.x; a[i+1]=t.y; a[i+2]=t.z; a[i+3]=t.w;
            }
#pragma unroll
            for (int j = 0; j < TN; j += 4){
                float4 t = *(const float4*)&Bs[kk][tx*TN + j];
                b[j]=t.x; b[j+1]=t.y; b[j+2]=t.z; b[j+3]=t.w;
            }
#pragma unroll
            for (int i = 0; i < TM; i++)
#pragma unroll
                for (int j = 0; j < TN; j++)
                    acc[i][j] = fmaf(a[i], b[j], acc[i][j]);
        }
        __syncthreads();
    }

    if (EPI == 0){
#pragma unroll
        for (int i = 0; i < TM; i++){
            int o = oBase + ty*TM + i;
            if (o >= M) continue;
            float bo = (o < rowSplit) ? biasa[o] : biasb[o - rowSplit];
#pragma unroll
            for (int j = 0; j < TN; j += 4){
                float4 r = make_float4(acc[i][j]+bo, acc[i][j+1]+bo,
                                       acc[i][j+2]+bo, acc[i][j+3]+bo);
                *(float4*)(Y + bz*sY + (long long)o*N + pBase + tx*TN + j) = r;
            }
        }
    } else if (EPI == 1){
#pragma unroll
        for (int i = 0; i < TM; i++){
            int o = oBase + ty*TM + i;
            if (o >= M) continue;
            float bo = biasa[o];
#pragma unroll
            for (int j = 0; j < TN; j += 4){
                long long off = (long long)o*N + pBase + tx*TN + j;
                float4 gp = *(const float4*)(ep_g + bz*s_g + off);
                float4 xr = *(const float4*)(ep_x + bz*s_x + off);
                float g0 = 1.0f/(1.0f+expf(-gp.x));
                float g1 = 1.0f/(1.0f+expf(-gp.y));
                float g2 = 1.0f/(1.0f+expf(-gp.z));
                float g3 = 1.0f/(1.0f+expf(-gp.w));
                float4 r;
                r.x = g0*(acc[i][j+0]+bo) + (1.0f-g0)*xr.x;
                r.y = g1*(acc[i][j+1]+bo) + (1.0f-g1)*xr.y;
                r.z = g2*(acc[i][j+2]+bo) + (1.0f-g2)*xr.z;
                r.w = g3*(acc[i][j+3]+bo) + (1.0f-g3)*xr.w;
                *(float4*)(Y + bz*sY + off) = r;
            }
        }
    } else { // EPI == 2 : q projection (gelu, reduce over pixels, write tile partial)
#pragma unroll
        for (int i = 0; i < TM; i++){
            int o = oBase + ty*TM + i;
            float s = 0.f;
            if (o < M){
                float bo = biasa[o];
#pragma unroll
                for (int j = 0; j < TN; j++) s += gelu_f(acc[i][j] + bo);
            }
            Red[ty*TM + i][tx] = s;
        }
        __syncthreads();
        if (tid < TBM){
            float s = 0.f;
#pragma unroll
            for (int t = 0; t < 16; t++) s += Red[tid][t];
            int o = oBase + tid;
            if (o < M)
                ep_qp[((bz*KDIM) + o)*64 + blockIdx.x] = s;
        }
    }
}

// ---------------- attention: q reduce, cosine sims, top-2, softmax ----------------
__global__ void attn_kernel(const float* __restrict__ mem_keys){
    __shared__ float qs[BB*KDIM];
    int tid = threadIdx.x;
    for (int idx = tid; idx < BB*KDIM; idx += 256){
        const float* p = g_qp + (long long)idx*64;
        float s = 0.f;
        for (int t = 0; t < 64; t++) s += p[t];
        qs[idx] = s * (1.0f/4096.0f);
    }
    __syncthreads();
    if (tid < BB){
        int b = tid;
        const float* q = qs + b*KDIM;
        float qn = 0.f;
        for (int j = 0; j < KDIM; j++) qn += q[j]*q[j];
        qn = fmaxf(sqrtf(qn), 1e-12f);
        float v[MR];
        for (int m = 0; m < MR; m++){
            const float* kk = mem_keys + m*KDIM;
            float kn = 0.f, d = 0.f;
            for (int j = 0; j < KDIM; j++){ kn += kk[j]*kk[j]; d += q[j]*kk[j]; }
            kn = fmaxf(sqrtf(kn), 1e-12f);
            v[m] = d/(qn*kn);
        }
        int i0 = 0;
        for (int m = 1; m < MR; m++) if (v[m] > v[i0]) i0 = m;
        int i1 = -1;
        for (int m = 0; m < MR; m++){
            if (m == i0) continue;
            if (i1 < 0 || v[m] > v[i1]) i1 = m;
        }
        float e1 = expf((v[i1]-v[i0])*10.0f);   // / TEMPERATURE(0.1), max-subtracted
        float a0 = 1.0f/(1.0f+e1);
        float a1 = e1/(1.0f+e1);
        g_attnw[b*2] = a0; g_attnw[b*2+1] = a1;
        g_attni[b*2] = i0; g_attni[b*2+1] = i1;
    }
}

// ---------------- bilinear 8->64 upsample + gelu + depthwise 3x3 (per m,c plane) ----------------
__global__ __launch_bounds__(256) void up_gelu_dw(
    const float* __restrict__ wdw, const float* __restrict__ bdw)
{
    int m = blockIdx.x / CC, c = blockIdx.x % CC;
    __shared__ float sm[64][65];
    __shared__ float tt[64];
    int tid = threadIdx.x;
    if (tid < 64) tt[tid] = g_t[((long long)m*CC + c)*64 + tid];
    __syncthreads();
    for (int i = tid; i < 1024; i += 256){
        int p = i << 2, h = p >> 6, w0 = p & 63;
        float shf = h*0.125f - 0.4375f;          // (h+0.5)/8 - 0.5
        int ih = (int)floorf(shf);
        float fh = shf - (float)ih;
        int h0 = ih < 0 ? 0 : ih;
        int h1 = (ih+1 > 7) ? 7 : ih+1;
#pragma unroll
        for (int q2 = 0; q2 < 4; q2++){
            int w = w0 + q2;
            float swf = w*0.125f - 0.4375f;
            int iw = (int)floorf(swf);
            float fw = swf - (float)iw;
            int wA = iw < 0 ? 0 : iw;
            int wB = (iw+1 > 7) ? 7 : iw+1;
            float top = (1.f-fw)*tt[h0*8+wA] + fw*tt[h0*8+wB];
            float bot = (1.f-fw)*tt[h1*8+wA] + fw*tt[h1*8+wB];
            float v = (1.f-fh)*top + fh*bot;
            sm[h][w] = gelu_f(v);
        }
    }
    __syncthreads();
    float w9[9];
#pragma unroll
    for (int t = 0; t < 9; t++) w9[t] = wdw[c*9+t];
    float bb = bdw[c];
    float* dst = g_dec + ((long long)m*CC + c)*HW;
    for (int i = tid; i < 1024; i += 256){
        int p = i << 2, h = p >> 6, w0 = p & 63;
        float ov[4];
#pragma unroll
        for (int q2 = 0; q2 < 4; q2++){
            int w = w0 + q2;
            float s = bb;
#pragma unroll
            for (int ky = 0; ky < 3; ky++){
                int hh = h + ky - 1;
                if ((unsigned)hh > 63u) continue;
#pragma unroll
                for (int kx = 0; kx < 3; kx++){
                    int ww = w + kx - 1;
                    if ((unsigned)ww > 63u) continue;
                    s = fmaf(w9[ky*3+kx], sm[hh][ww], s);
                }
            }
            ov[q2] = s;
        }
        *(float4*)(dst + p) = make_float4(ov[0], ov[1], ov[2], ov[3]);
    }
}

// ---------------- weighted reference gather ----------------
__global__ void wref_kernel(){
    long long idx = (long long)blockIdx.x*blockDim.x + threadIdx.x;  // float4 index
    long long e = idx << 2;
    int b = (int)(e / ((long long)CC*HW));
    long long r = e - (long long)b*CC*HW;
    float a0 = g_attnw[b*2], a1 = g_attnw[b*2+1];
    const float4 d0 = *(const float4*)(g_dec + (long long)g_attni[b*2]  *CC*HW + r);
    const float4 d1 = *(const float4*)(g_dec + (long long)g_attni[b*2+1]*CC*HW + r);
    float4 o;
    o.x = a0*d0.x + a1*d1.x;
    o.y = a0*d0.y + a1*d1.y;
    o.z = a0*d0.z + a1*d1.z;
    o.w = a0*d0.w + a1*d1.w;
    *(float4*)(g_wref + e) = o;
}

// ---------------- group-norm statistics ----------------
__global__ void gn_stats(){
    int b = blockIdx.x >> 5, g = blockIdx.x & 31;
    int tid = threadIdx.x;
    const float4* p = (const float4*)(g_big + ((long long)b*2*CC + g*CPG)*HW);
    const int n4 = CPG*HW/4;  // 20480
    float s = 0.f, ss = 0.f;
    for (int i = tid; i < n4; i += 256){
        float4 v = p[i];
        s  += v.x + v.y + v.z + v.w;
        ss += v.x*v.x + v.y*v.y + v.z*v.z + v.w*v.w;
    }
    __shared__ float sh1[256], sh2[256];
    sh1[tid] = s; sh2[tid] = ss;
    __syncthreads();
    for (int st = 128; st > 0; st >>= 1){
        if (tid < st){ sh1[tid] += sh1[tid+st]; sh2[tid] += sh2[tid+st]; }
        __syncthreads();
    }
    if (tid == 0){
        const float inv = 1.0f/(CPG*HW);
        float mu = sh1[0]*inv;
        float var = sh2[0]*inv - mu*mu;
        g_gn[blockIdx.x*2]   = mu;
        g_gn[blockIdx.x*2+1] = rsqrtf(var + 1e-5f);
    }
}

// ---------------- group-norm + gelu + depthwise 3x3 (per b,c plane) ----------------
__global__ __launch_bounds__(256) void gn_gelu_dw(
    const float* __restrict__ gamma, const float* __restrict__ beta,
    const float* __restrict__ wdw, const float* __restrict__ bdw)
{
    int b = blockIdx.x / CC, c = blockIdx.x % CC;
    __shared__ float sm[64][65];
    int tid = threadIdx.x;
    const float* src = g_big + ((long long)b*2*CC + c)*HW;
    int g = c / CPG;
    float mu = g_gn[(b*GROUPS+g)*2], rs = g_gn[(b*GROUPS+g)*2+1];
    float ga = gamma[c]*rs;
    float be = beta[c] - mu*ga;
    for (int i = tid; i < 1024; i += 256){
        float4 v = ((const float4*)src)[i];
        int p = i << 2, h = p >> 6, w0 = p & 63;
        sm[h][w0]   = gelu_f(v.x*ga + be);
        sm[h][w0+1] = gelu_f(v.y*ga + be);
        sm[h][w0+2] = gelu_f(v.z*ga + be);
        sm[h][w0+3] = gelu_f(v.w*ga + be);
    }
    __syncthreads();
    float w9[9];
#pragma unroll
    for (int t = 0; t < 9; t++) w9[t] = wdw[c*9+t];
    float bb = bdw[c];
    float* dst = g_f2 + ((long long)b*CC + c)*HW;
    for (int i = tid; i < 1024; i += 256){
        int p = i << 2, h = p >> 6, w0 = p & 63;
        float ov[4];
#pragma unroll
        for (int q2 = 0; q2 < 4; q2++){
            int w = w0 + q2;
            float s = bb;
#pragma unroll
            for (int ky = 0; ky < 3; ky++){
                int hh = h + ky - 1;
                if ((unsigned)hh > 63u) continue;
#pragma unroll
                for (int kx = 0; kx < 3; kx++){
                    int ww = w + kx - 1;
                    if ((unsigned)ww > 63u) continue;
                    s = fmaf(w9[ky*3+kx], sm[hh][ww], s);
                }
            }
            ov[q2] = s;
        }
        *(float4*)(dst + p) = make_float4(ov[0], ov[1], ov[2], ov[3]);
    }
}

// ---------------- host launcher ----------------
extern "C" void kernel_launch(void* const* d_in, const int* in_sizes, int n_in,
                              void* d_out, int out_size)
{
    const float* x         = (const float*)d_in[0];
    const float* qp_w      = (const float*)d_in[1];
    const float* qp_b      = (const float*)d_in[2];
    const float* mem_keys  = (const float*)d_in[3];
    const float* mem_values= (const float*)d_in[4];
    const float* vd_w1     = (const float*)d_in[5];
    const float* vd_b1     = (const float*)d_in[6];
    const float* vd_wdw    = (const float*)d_in[7];
    const float* vd_bdw    = (const float*)d_in[8];
    const float* fn_w1     = (const float*)d_in[9];
    const float* fn_b1     = (const float*)d_in[10];
    const float* fn_gamma  = (const float*)d_in[11];
    const float* fn_beta   = (const float*)d_in[12];
    const float* fn_wdw    = (const float*)d_in[13];
    const float* fn_bdw    = (const float*)d_in[14];
    const float* fn_w2     = (const float*)d_in[15];
    const float* fn_b2     = (const float*)d_in[16];
    const float* fg_w      = (const float*)d_in[17];
    const float* fg_b      = (const float*)d_in[18];
    float* out = (float*)d_out;
    (void)in_sizes; (void)n_in; (void)out_size;

    float *p_t, *p_big, *p_f2, *p_qp, *p_wref;
    cudaGetSymbolAddress((void**)&p_t,    g_t);
    cudaGetSymbolAddress((void**)&p_big,  g_big);
    cudaGetSymbolAddress((void**)&p_f2,   g_f2);
    cudaGetSymbolAddress((void**)&p_qp,   g_qp);
    cudaGetSymbolAddress((void**)&p_wref, g_wref);

    const long long sX = (long long)CC*HW;

    // 1) t[m] = vd_w1 @ mem_values[m] + vd_b1  (at 8x8 resolution)
    gemm_tpl<64,64,0><<<dim3(1,10,MR),256>>>(
        vd_w1, vd_w1, CC,
        mem_values, (long long)CC*64, mem_values, (long long)CC*64, CC,
        vd_b1, vd_b1,
        p_t, (long long)CC*64,
        CC, 64, CC,
        nullptr,0,nullptr,0,nullptr);

    // 2) q-projection partials: gelu(qp_w@x + b) pixel-reduced per tile
    gemm_tpl<64,64,2><<<dim3(64,3,BB),256>>>(
        qp_w, qp_w, KDIM,
        x, sX, x, sX, CC,
        qp_b, qp_b,
        nullptr, 0,
        KDIM, HW, CC,
        nullptr,0,nullptr,0,p_qp);

    // 3) cosine attention, top-2, softmax
    attn_kernel<<<1,256>>>(mem_keys);

    // 4) upsample + gelu + depthwise per memory row
    up_gelu_dw<<<MR*CC,256>>>(vd_wdw, vd_bdw);

    // 5) weighted reference
    wref_kernel<<<(BB*CC*HW/4)/256,256>>>();

    // 6) fused fn1 + gate GEMM over [x ; wref]
    gemm_tpl<128,128,0><<<dim3(32,10,BB),256>>>(
        fn_w1, fg_w, CC,
        x, sX, p_wref, sX, CC,
        fn_b1, fg_b,
        p_big, (long long)2*CC*HW,
        2*CC, HW, 2*CC,
        nullptr,0,nullptr,0,nullptr);

    // 7) group-norm stats
    gn_stats<<<BB*GROUPS,256>>>();

    // 8) gn + gelu + depthwise
    gn_gelu_dw<<<BB*CC,256>>>(fn_gamma, fn_beta, fn_wdw, fn_bdw);

    // 9) fn2 GEMM + sigmoid-gate blend epilogue -> out
    gemm_tpl<128,128,1><<<dim3(32,5,BB),256>>>(
        fn_w2, fn_w2, CC,
        p_f2, sX, p_f2, sX, CC,
        fn_b2, fn_b2,
        out, sX,
        CC, HW, CC,
        p_big + (long long)CC*HW, (long long)2*CC*HW,
        x, sX,
        nullptr);
}

// round 2
// speedup vs baseline: 1.0012x; 1.0012x over previous
#include <cuda_runtime.h>
#include <math.h>

// ---------------- problem constants ----------------
#define BB 8
#define CC 640
#define HW 4096     // 64*64
#define KDIM 160
#define MR 4
#define GROUPS 32
#define CPG 20      // 640/32

// ---------------- scratch (device globals; no allocs allowed) ----------------
__device__ float g_t   [MR*CC*64];          // 8x8 conv1x1 result per memory row
__device__ float g_dec [MR*CC*HW];          // decoded refs per memory row
__device__ float g_wref[BB*CC*HW];          // weighted reference
__device__ float g_big [BB*2*CC*HW];        // rows 0..639: f1 ; rows 640..1279: gate-pre
__device__ float g_f2  [BB*CC*HW];          // after gn+gelu+dwconv
__device__ float g_qp  [BB*KDIM*64];        // q-pool partials (64 pixel-tiles)
__device__ float g_gn  [BB*GROUPS*2];       // mu, rsigma per (b,group)
__device__ float g_attnw[BB*2];
__device__ int   g_attni[BB*2];

__device__ __forceinline__ float gelu_f(float v){
    return 0.5f*v*(1.0f + erff(v*0.70710678118654752f));
}

// ---------------- generic tiled SGEMM ----------------
// Y[bz, o, p] = sum_c W[o,c] * X[bz,c,p] + bias[o]
// W rows split across (Wa,Wb) at rowSplit; X channels split across (Xa,Xb) at chanSplit.
// EPI: 0 = plain store, 1 = final (sigmoid-gate blend), 2 = q-projection (gelu + pixel reduce)
constexpr int GK = 16;

template<int TBM, int TBN, int EPI>
__global__ __launch_bounds__(256) void gemm_tpl(
    const float* __restrict__ Wa, const float* __restrict__ Wb, int rowSplit,
    const float* __restrict__ Xa, long long sXa,
    const float* __restrict__ Xb, long long sXb, int chanSplit,
    const float* __restrict__ biasa, const float* __restrict__ biasb,
    float* __restrict__ Y, long long sY,
    int M, int N, int K,
    const float* __restrict__ ep_g, long long s_g,
    const float* __restrict__ ep_x, long long s_x,
    float* __restrict__ ep_qp)
{
    constexpr int TM = TBM/16, TN = TBN/16;
    __shared__ float As[GK][TBM];
    __shared__ float Bs[GK][TBN];
    __shared__ float Red[TBM][17];

    const int tid = threadIdx.x;
    const int tx = tid & 15, ty = tid >> 4;
    const int pBase = blockIdx.x * TBN;
    const int oBase = blockIdx.y * TBM;
    const int bz = blockIdx.z;

    float acc[TM][TN];
#pragma unroll
    for (int i = 0; i < TM; i++)
#pragma unroll
        for (int j = 0; j < TN; j++) acc[i][j] = 0.f;

    for (int c0 = 0; c0 < K; c0 += GK){
        // load A tile (transposed into As[k][m])
#pragma unroll
        for (int l = 0; l < TBM/64; l++){
            int i = (tid >> 2) + l*64;
            int j4 = (tid & 3) << 2;
            int o = oBase + i;
            float4 w = make_float4(0.f,0.f,0.f,0.f);
            if (o < M){
                const float* wp = (o < rowSplit) ? (Wa + (long long)o*K)
                                                 : (Wb + (long long)(o-rowSplit)*K);
                w = *(const float4*)(wp + c0 + j4);
            }
            As[j4+0][i] = w.x; As[j4+1][i] = w.y; As[j4+2][i] = w.z; As[j4+3][i] = w.w;
        }
        // load B tile
#pragma unroll
        for (int l = 0; l < TBN/64; l++){
            int j = tid >> 4;
            int n4 = ((tid & 15) << 2) + l*64;
            int c = c0 + j;
            const float* xp = (c < chanSplit) ? (Xa + bz*sXa + (long long)c*N)
                                              : (Xb + bz*sXb + (long long)(c - chanSplit)*N);
            *(float4*)&Bs[j][n4] = *(const float4*)(xp + pBase + n4);
        }
        __syncthreads();
#pragma unroll
        for (int kk = 0; kk < GK; kk++){
            float a[TM], b[TN];
#pragma unroll
            for (int i = 0; i < TM; i += 4){
                float4 t = *(const float4*)&As[kk][ty*TM + i];
                a[i]=t.x; a[i+1]=t.y; a[i+2]=t.z; a[i+3]=t.w;
            }
#pragma unroll
            for (int j = 0; j < TN; j += 4){
                float4 t = *(const float4*)&Bs[kk][tx*TN + j];
                b[j]=t.x; b[j+1]=t.y; b[j+2]=t.z; b[j+3]=t.w;
            }
#pragma unroll
            for (int i = 0; i < TM; i++)
#pragma unroll
                for (int j = 0; j < TN; j++)
                    acc[i][j] = fmaf(a[i], b[j], acc[i][j]);
        }
        __syncthreads();
    }

    if (EPI == 0){
#pragma unroll
        for (int i = 0; i < TM; i++){
            int o = oBase + ty*TM + i;
            if (o >= M) continue;
            float bo = (o < rowSplit) ? biasa[o] : biasb[o - rowSplit];
#pragma unroll
            for (int j = 0; j < TN; j += 4){
                float4 r = make_float4(acc[i][j]+bo, acc[i][j+1]+bo,
                                       acc[i][j+2]+bo, acc[i][j+3]+bo);
                *(float4*)(Y + bz*sY + (long long)o*N + pBase + tx*TN + j) = r;
            }
        }
    } else if (EPI == 1){
#pragma unroll
        for (int i = 0; i < TM; i++){
            int o = oBase + ty*TM + i;
            if (o >= M) continue;
            float bo = biasa[o];
#pragma unroll
            for (int j = 0; j < TN; j += 4){
                long long off = (long long)o*N + pBase + tx*TN + j;
                float4 gp = *(const float4*)(ep_g + bz*s_g + off);
                float4 xr = *(const float4*)(ep_x + bz*s_x + off);
                float g0 = 1.0f/(1.0f+expf(-gp.x));
                float g1 = 1.0f/(1.0f+expf(-gp.y));
                float g2 = 1.0f/(1.0f+expf(-gp.z));
                float g3 = 1.0f/(1.0f+expf(-gp.w));
                float4 r;
                r.x = g0*(acc[i][j+0]+bo) + (1.0f-g0)*xr.x;
                r.y = g1*(acc[i][j+1]+bo) + (1.0f-g1)*xr.y;
                r.z = g2*(acc[i][j+2]+bo) + (1.0f-g2)*xr.z;
                r.w = g3*(acc[i][j+3]+bo) + (1.0f-g3)*xr.w;
                *(float4*)(Y + bz*sY + off) = r;
            }
        }
    } else { // EPI == 2 : q projection (gelu, reduce over pixels, write tile partial)
#pragma unroll
        for (int i = 0; i < TM; i++){
            int o = oBase + ty*TM + i;
            float s = 0.f;
            if (o < M){
                float bo = biasa[o];
#pragma unroll
                for (int j = 0; j < TN; j++) s += gelu_f(acc[i][j] + bo);
            }
            Red[ty*TM + i][tx] = s;
        }
        __syncthreads();
        if (tid < TBM){
            float s = 0.f;
#pragma unroll
            for (int t = 0; t < 16; t++) s += Red[tid][t];
            int o = oBase + tid;
            if (o < M)
                ep_qp[((bz*KDIM) + o)*64 + blockIdx.x] = s;
        }
    }
}

// ---------------- attention: q reduce, cosine sims, top-2, softmax ----------------
__global__ void attn_kernel(const float* __restrict__ mem_keys){
    __shared__ float qs[BB*KDIM];
    int tid = threadIdx.x;
    for (int idx = tid; idx < BB*KDIM; idx += 256){
        const float* p = g_qp + (long long)idx*64;
        float s = 0.f;
        for (int t = 0; t < 64; t++) s += p[t];
        qs[idx] = s * (1.0f/4096.0f);
    }
    __syncthreads();
    if (tid < BB){
        int b = tid;
        const float* q = qs + b*KDIM;
        float qn = 0.f;
        for (int j = 0; j < KDIM; j++) qn += q[j]*q[j];
        qn = fmaxf(sqrtf(qn), 1e-12f);
        float v[MR];
        for (int m = 0; m < MR; m++){
            const float* kk = mem_keys + m*KDIM;
            float kn = 0.f, d = 0.f;
            for (int j = 0; j < KDIM; j++){ kn += kk[j]*kk[j]; d += q[j]*kk[j]; }
            kn = fmaxf(sqrtf(kn), 1e-12f);
            v[m] = d/(qn*kn);
        }
        int i0 = 0;
        for (int m = 1; m < MR; m++) if (v[m] > v[i0]) i0 = m;
        int i1 = -1;
        for (int m = 0; m < MR; m++){
            if (m == i0) continue;
            if (i1 < 0 || v[m] > v[i1]) i1 = m;
        }
        float e1 = expf((v[i1]-v[i0])*10.0f);   // / TEMPERATURE(0.1), max-subtracted
        float a0 = 1.0f/(1.0f+e1);
        float a1 = e1/(1.0f+e1);
        g_attnw[b*2] = a0; g_attnw[b*2+1] = a1;
        g_attni[b*2] = i0; g_attni[b*2+1] = i1;
    }
}

// ---------------- bilinear 8->64 upsample + gelu + depthwise 3x3 (per m,c plane) ----------------
__global__ __launch_bounds__(256) void up_gelu_dw(
    const float* __restrict__ wdw, const float* __restrict__ bdw)
{
    int m = blockIdx.x / CC, c = blockIdx.x % CC;
    __shared__ float sm[64][65];
    __shared__ float tt[64];
    int tid = threadIdx.x;
    if (tid < 64) tt[tid] = g_t[((long long)m*CC + c)*64 + tid];
    __syncthreads();
    for (int i = tid; i < 1024; i += 256){
        int p = i << 2, h = p >> 6, w0 = p & 63;
        float shf = h*0.125f - 0.4375f;          // (h+0.5)/8 - 0.5
        int ih = (int)floorf(shf);
        float fh = shf - (float)ih;
        int h0 = ih < 0 ? 0 : ih;
        int h1 = (ih+1 > 7) ? 7 : ih+1;
#pragma unroll
        for (int q2 = 0; q2 < 4; q2++){
            int w = w0 + q2;
            float swf = w*0.125f - 0.4375f;
            int iw = (int)floorf(swf);
            float fw = swf - (float)iw;
            int wA = iw < 0 ? 0 : iw;
            int wB = (iw+1 > 7) ? 7 : iw+1;
            float top = (1.f-fw)*tt[h0*8+wA] + fw*tt[h0*8+wB];
            float bot = (1.f-fw)*tt[h1*8+wA] + fw*tt[h1*8+wB];
            float v = (1.f-fh)*top + fh*bot;
            sm[h][w] = gelu_f(v);
        }
    }
    __syncthreads();
    float w9[9];
#pragma unroll
    for (int t = 0; t < 9; t++) w9[t] = wdw[c*9+t];
    float bb = bdw[c];
    float* dst = g_dec + ((long long)m*CC + c)*HW;
    for (int i = tid; i < 1024; i += 256){
        int p = i << 2, h = p >> 6, w0 = p & 63;
        float ov[4];
#pragma unroll
        for (int q2 = 0; q2 < 4; q2++){
            int w = w0 + q2;
            float s = bb;
#pragma unroll
            for (int ky = 0; ky < 3; ky++){
                int hh = h + ky - 1;
                if ((unsigned)hh > 63u) continue;
#pragma unroll
                for (int kx = 0; kx < 3; kx++){
                    int ww = w + kx - 1;
                    if ((unsigned)ww > 63u) continue;
                    s = fmaf(w9[ky*3+kx], sm[hh][ww], s);
                }
            }
            ov[q2] = s;
        }
        *(float4*)(dst + p) = make_float4(ov[0], ov[1], ov[2], ov[3]);
    }
}

// ---------------- weighted reference gather ----------------
__global__ void wref_kernel(){
    long long idx = (long long)blockIdx.x*blockDim.x + threadIdx.x;  // float4 index
    long long e = idx << 2;
    int b = (int)(e / ((long long)CC*HW));
    long long r = e - (long long)b*CC*HW;
    float a0 = g_attnw[b*2], a1 = g_attnw[b*2+1];
    const float4 d0 = *(const float4*)(g_dec + (long long)g_attni[b*2]  *CC*HW + r);
    const float4 d1 = *(const float4*)(g_dec + (long long)g_attni[b*2+1]*CC*HW + r);
    float4 o;
    o.x = a0*d0.x + a1*d1.x;
    o.y = a0*d0.y + a1*d1.y;
    o.z = a0*d0.z + a1*d1.z;
    o.w = a0*d0.w + a1*d1.w;
    *(float4*)(g_wref + e) = o;
}

// ---------------- group-norm statistics ----------------
__global__ void gn_stats(){
    int b = blockIdx.x >> 5, g = blockIdx.x & 31;
    int tid = threadIdx.x;
    const float4* p = (const float4*)(g_big + ((long long)b*2*CC + g*CPG)*HW);
    const int n4 = CPG*HW/4;  // 20480
    float s = 0.f, ss = 0.f;
    for (int i = tid; i < n4; i += 256){
        float4 v = p[i];
        s  += v.x + v.y + v.z + v.w;
        ss += v.x*v.x + v.y*v.y + v.z*v.z + v.w*v.w;
    }
    __shared__ float sh1[256], sh2[256];
    sh1[tid] = s; sh2[tid] = ss;
    __syncthreads();
    for (int st = 128; st > 0; st >>= 1){
        if (tid < st){ sh1[tid] += sh1[tid+st]; sh2[tid] += sh2[tid+st]; }
        __syncthreads();
    }
    if (tid == 0){
        const float inv = 1.0f/(CPG*HW);
        float mu = sh1[0]*inv;
        float var = sh2[0]*inv - mu*mu;
        g_gn[blockIdx.x*2]   = mu;
        g_gn[blockIdx.x*2+1] = rsqrtf(var + 1e-5f);
    }
}

// ---------------- group-norm + gelu + depthwise 3x3 (per b,c plane) ----------------
__global__ __launch_bounds__(256) void gn_gelu_dw(
    const float* __restrict__ gamma, const float* __restrict__ beta,
    const float* __restrict__ wdw, const float* __restrict__ bdw)
{
    int b = blockIdx.x / CC, c = blockIdx.x % CC;
    __shared__ float sm[64][65];
    int tid = threadIdx.x;
    const float* src = g_big + ((long long)b*2*CC + c)*HW;
    int g = c / CPG;
    float mu = g_gn[(b*GROUPS+g)*2], rs = g_gn[(b*GROUPS+g)*2+1];
    float ga = gamma[c]*rs;
    float be = beta[c] - mu*ga;
    for (int i = tid; i < 1024; i += 256){
        float4 v = ((const float4*)src)[i];
        int p = i << 2, h = p >> 6, w0 = p & 63;
        sm[h][w0]   = gelu_f(v.x*ga + be);
        sm[h][w0+1] = gelu_f(v.y*ga + be);
        sm[h][w0+2] = gelu_f(v.z*ga + be);
        sm[h][w0+3] = gelu_f(v.w*ga + be);
    }
    __syncthreads();
    float w9[9];
#pragma unroll
    for (int t = 0; t < 9; t++) w9[t] = wdw[c*9+t];
    float bb = bdw[c];
    float* dst = g_f2 + ((long long)b*CC + c)*HW;
    for (int i = tid; i < 1024; i += 256){
        int p = i << 2, h = p >> 6, w0 = p & 63;
        float ov[4];
#pragma unroll
        for (int q2 = 0; q2 < 4; q2++){
            int w = w0 + q2;
            float s = bb;
#pragma unroll
            for (int ky = 0; ky < 3; ky++){
                int hh = h + ky - 1;
                if ((unsigned)hh > 63u) continue;
#pragma unroll
                for (int kx = 0; kx < 3; kx++){
                    int ww = w + kx - 1;
                    if ((unsigned)ww > 63u) continue;
                    s = fmaf(w9[ky*3+kx], sm[hh][ww], s);
                }
            }
            ov[q2] = s;
        }
        *(float4*)(dst + p) = make_float4(ov[0], ov[1], ov[2], ov[3]);
    }
}

// ---------------- host launcher ----------------
extern "C" void kernel_launch(void* const* d_in, const int* in_sizes, int n_in,
                              void* d_out, int out_size)
{
    const float* x         = (const float*)d_in[0];
    const float* qp_w      = (const float*)d_in[1];
    const float* qp_b      = (const float*)d_in[2];
    const float* mem_keys  = (const float*)d_in[3];
    const float* mem_values= (const float*)d_in[4];
    const float* vd_w1     = (const float*)d_in[5];
    const float* vd_b1     = (const float*)d_in[6];
    const float* vd_wdw    = (const float*)d_in[7];
    const float* vd_bdw    = (const float*)d_in[8];
    const float* fn_w1     = (const float*)d_in[9];
    const float* fn_b1     = (const float*)d_in[10];
    const float* fn_gamma  = (const float*)d_in[11];
    const float* fn_beta   = (const float*)d_in[12];
    const float* fn_wdw    = (const float*)d_in[13];
    const float* fn_bdw    = (const float*)d_in[14];
    const float* fn_w2     = (const float*)d_in[15];
    const float* fn_b2     = (const float*)d_in[16];
    const float* fg_w      = (const float*)d_in[17];
    const float* fg_b      = (const float*)d_in[18];
    float* out = (float*)d_out;
    (void)in_sizes; (void)n_in; (void)out_size;

    float *p_t, *p_big, *p_f2, *p_qp, *p_wref;
    cudaGetSymbolAddress((void**)&p_t,    g_t);
    cudaGetSymbolAddress((void**)&p_big,  g_big);
    cudaGetSymbolAddress((void**)&p_f2,   g_f2);
    cudaGetSymbolAddress((void**)&p_qp,   g_qp);
    cudaGetSymbolAddress((void**)&p_wref, g_wref);

    const long long sX = (long long)CC*HW;

    // 1) t[m] = vd_w1 @ mem_values[m] + vd_b1  (at 8x8 resolution)
    gemm_tpl<64,64,0><<<dim3(1,10,MR),256>>>(
        vd_w1, vd_w1, CC,
        mem_values, (long long)CC*64, mem_values, (long long)CC*64, CC,
        vd_b1, vd_b1,
        p_t, (long long)CC*64,
        CC, 64, CC,
        nullptr,0,nullptr,0,nullptr);

    // 2) q-projection partials: gelu(qp_w@x + b) pixel-reduced per tile
    gemm_tpl<64,64,2><<<dim3(64,3,BB),256>>>(
        qp_w, qp_w, KDIM,
        x, sX, x, sX, CC,
        qp_b, qp_b,
        nullptr, 0,
        KDIM, HW, CC,
        nullptr,0,nullptr,0,p_qp);

    // 3) cosine attention, top-2, softmax
    attn_kernel<<<1,256>>>(mem_keys);

    // 4) upsample + gelu + depthwise per memory row
    up_gelu_dw<<<MR*CC,256>>>(vd_wdw, vd_bdw);

    // 5) weighted reference
    wref_kernel<<<(BB*CC*HW/4)/256,256>>>();

    // 6) fused fn1 + gate GEMM over [x ; wref]
    gemm_tpl<128,128,0><<<dim3(32,10,BB),256>>>(
        fn_w1, fg_w, CC,
        x, sX, p_wref, sX, CC,
        fn_b1, fg_b,
        p_big, (long long)2*CC*HW,
        2*CC, HW, 2*CC,
        nullptr,0,nullptr,0,nullptr);

    // 7) group-norm stats
    gn_stats<<<BB*GROUPS,256>>>();

    // 8) gn + gelu + depthwise
    gn_gelu_dw<<<BB*CC,256>>>(fn_gamma, fn_beta, fn_wdw, fn_bdw);

    // 9) fn2 GEMM + sigmoid-gate blend epilogue -> out
    gemm_tpl<128,128,1><<<dim3(32,5,BB),256>>>(
        fn_w2, fn_w2, CC,
        p_f2, sX, p_f2, sX, CC,
        fn_b2, fn_b2,
        out, sX,
        CC, HW, CC,
        p_big + (long long)CC*HW, (long long)2*CC*HW,
        x, sX,
        nullptr);
}

// round 4
// speedup vs baseline: 1.5985x; 1.5966x over previous
#include <cuda_runtime.h>
#include <cuda_bf16.h>
#include <math.h>
#include <stdint.h>

// ---------------- problem constants ----------------
#define BB 8
#define CC 640
#define HW 4096     // 64*64
#define KDIM 160
#define MR 4
#define GROUPS 32
#define CPG 20      // 640/32

// ---------------- scratch (device globals; no allocs allowed) ----------------
__device__ float g_t   [MR*CC*64];
__device__ float g_dec [MR*CC*HW];
__device__ float g_big [BB*2*CC*HW];
__device__ float g_f2  [BB*CC*HW];
__device__ float g_qp  [BB*KDIM*64];
__device__ float g_gn  [BB*GROUPS*2];
__device__ float g_attnw[BB*2];
__device__ int   g_attni[BB*2];

// bf16 split operands for tensor-core GEMMs
__device__ __nv_bfloat16 g_whi [2*CC*2*CC];
__device__ __nv_bfloat16 g_wlo [2*CC*2*CC];
__device__ __nv_bfloat16 g_w2hi[CC*CC];
__device__ __nv_bfloat16 g_w2lo[CC*CC];
__device__ __nv_bfloat16 g_bthi[(long long)BB*HW*2*CC];
__device__ __nv_bfloat16 g_btlo[(long long)BB*HW*2*CC];
__device__ __nv_bfloat16 g_fthi[(long long)BB*HW*CC];
__device__ __nv_bfloat16 g_ftlo[(long long)BB*HW*CC];

__device__ __forceinline__ float gelu_f(float v){
    return 0.5f*v*(1.0f + erff(v*0.70710678118654752f));
}

// ================= mma.sync helpers (sm_80+ base ISA) =================
__device__ __forceinline__ uint32_t smem_u32(const void* p){
    uint32_t a;
    asm("{ .reg .u64 t; cvta.to.shared.u64 t, %1; cvt.u32.u64 %0, t; }" : "=r"(a) : "l"(p));
    return a;
}
__device__ __forceinline__ void cpa16(uint32_t dst, const void* src){
    asm volatile("cp.async.cg.shared.global [%0], [%1], 16;" :: "r"(dst), "l"(src));
}
__device__ __forceinline__ void ldm_x4(uint32_t (&r)[4], uint32_t addr){
    asm volatile("ldmatrix.sync.aligned.m8n8.x4.shared.b16 {%0,%1,%2,%3}, [%4];"
        : "=r"(r[0]),"=r"(r[1]),"=r"(r[2]),"=r"(r[3]) : "r"(addr));
}
__device__ __forceinline__ void ldm_x2(uint32_t (&r)[2], uint32_t addr){
    asm volatile("ldmatrix.sync.aligned.m8n8.x2.shared.b16 {%0,%1}, [%2];"
        : "=r"(r[0]),"=r"(r[1]) : "r"(addr));
}
__device__ __forceinline__ void mma_bf16(float (&d)[4], const uint32_t (&a)[4], const uint32_t (&b)[2]){
    asm volatile("mma.sync.aligned.m16n8k16.row.col.f32.bf16.bf16.f32 "
        "{%0,%1,%2,%3}, {%4,%5,%6,%7}, {%8,%9}, {%0,%1,%2,%3};"
        : "+f"(d[0]),"+f"(d[1]),"+f"(d[2]),"+f"(d[3])
        : "r"(a[0]),"r"(a[1]),"r"(a[2]),"r"(a[3]), "r"(b[0]),"r"(b[1]));
}

// ================= split-bf16 tensor-core GEMM (mma.sync) =================
// Y[bz, o, p] = sum_k W[o,k] * B[bz, p, k] (+bias), W = Whi+Wlo, B = Bhi+Blo.
// CTA tile 128(M) x 128(N), K-chunks of 32, 2-stage cp.async pipeline.
// SMEM tile rows padded to 80B (conflict-free ldmatrix phases).
// EPI 0: plain store; EPI 1: sigmoid-gate blend with ep_g / ep_x.
#define KC 32
#define TPITCH 80           // bytes per smem tile row (64 data + 16 pad)
#define TILE_B (128*TPITCH) // 10240
#define STAGE_B (4*TILE_B)  // 40960

template<int EPI>
__global__ void __launch_bounds__(256) gemm_tc(
    const __nv_bfloat16* __restrict__ Whi, const __nv_bfloat16* __restrict__ Wlo,
    const __nv_bfloat16* __restrict__ Bhi, const __nv_bfloat16* __restrict__ Blo,
    const float* __restrict__ biasa, const float* __restrict__ biasb, int rowSplit,
    float* __restrict__ Y, long long sY, int K,
    const float* __restrict__ ep_g, long long s_g,
    const float* __restrict__ ep_x, long long s_x)
{
    extern __shared__ char smem[];
    const uint32_t sb = smem_u32(smem);
    const int tid = threadIdx.x, wid = tid >> 5, lane = tid & 31;
    const int warpM = wid >> 2, warpN = wid & 3;
    const int pBase = blockIdx.x * 128, oBase = blockIdx.y * 128, bz = blockIdx.z;
    const long long P = 4096;

    const __nv_bfloat16* ah_g = Whi + (long long)oBase * K;
    const __nv_bfloat16* al_g = Wlo + (long long)oBase * K;
    const __nv_bfloat16* bh_g = Bhi + ((long long)bz * P + pBase) * K;
    const __nv_bfloat16* bl_g = Blo + ((long long)bz * P + pBase) * K;

    float acc[4][4][4];
#pragma unroll
    for (int a = 0; a < 4; a++)
#pragma unroll
        for (int b = 0; b < 4; b++)
#pragma unroll
            for (int c = 0; c < 4; c++) acc[a][b][c] = 0.f;

    // ldmatrix base offsets (per-thread, within a tile)
    const uint32_t aoff = (uint32_t)((warpM*64 + (lane & 15)) * TPITCH + (lane >> 4) * 16);
    const uint32_t boff = (uint32_t)((warpN*32 + (lane & 7)) * TPITCH + ((lane >> 3) & 1) * 16);

    const int nCh = K / KC;

    // ---- stage loader ----
    auto load_stage = [&](int st, int c0){
        uint32_t base = sb + st * STAGE_B;
#pragma unroll
        for (int i = 0; i < 8; i++){
            int t = tid + (i << 8);
            int tile = t >> 9, u = t & 511, r = u >> 2, ck = u & 3;
            uint32_t dst = base + tile*TILE_B + (uint32_t)(r*TPITCH + ck*16);
            const __nv_bfloat16* gsrc =
                (tile == 0) ? ah_g : (tile == 1) ? al_g : (tile == 2) ? bh_g : bl_g;
            cpa16(dst, gsrc + (long long)r * K + c0 + (ck << 3));
        }
        asm volatile("cp.async.commit_group;" ::: "memory");
    };

    load_stage(0, 0);

    for (int ch = 0; ch < nCh; ch++){
        if (ch + 1 < nCh){
            load_stage((ch + 1) & 1, (ch + 1) * KC);
            asm volatile("cp.async.wait_group 1;" ::: "memory");
        } else {
            asm volatile("cp.async.wait_group 0;" ::: "memory");
        }
        __syncthreads();

        uint32_t base = sb + (ch & 1) * STAGE_B;
        uint32_t SAH = base, SAL = base + TILE_B, SBH = base + 2*TILE_B, SBL = base + 3*TILE_B;
#pragma unroll
        for (int ks = 0; ks < 2; ks++){
            uint32_t ko = ks * 32;   // 16 bf16 = 32 bytes
            uint32_t ah[4][4], al[4][4], bh[4][2], bl[4][2];
#pragma unroll
            for (int mi = 0; mi < 4; mi++){
                ldm_x4(ah[mi], SAH + aoff + mi*16*TPITCH + ko);
                ldm_x4(al[mi], SAL + aoff + mi*16*TPITCH + ko);
            }
#pragma unroll
            for (int ni = 0; ni < 4; ni++){
                ldm_x2(bh[ni], SBH + boff + ni*8*TPITCH + ko);
                ldm_x2(bl[ni], SBL + boff + ni*8*TPITCH + ko);
            }
#pragma unroll
            for (int mi = 0; mi < 4; mi++)
#pragma unroll
                for (int ni = 0; ni < 4; ni++) mma_bf16(acc[mi][ni], ah[mi], bh[ni]);
#pragma unroll
            for (int mi = 0; mi < 4; mi++)
#pragma unroll
                for (int ni = 0; ni < 4; ni++) mma_bf16(acc[mi][ni], ah[mi], bl[ni]);
#pragma unroll
            for (int mi = 0; mi < 4; mi++)
#pragma unroll
                for (int ni = 0; ni < 4; ni++) mma_bf16(acc[mi][ni], al[mi], bh[ni]);
        }
        __syncthreads();
    }

    // ---- epilogue: acc -> SMEM stage (pitch 132) -> coalesced global ----
    float* stage = (float*)smem;
#pragma unroll
    for (int mi = 0; mi < 4; mi++){
        int r0 = warpM*64 + mi*16 + (lane >> 2);
#pragma unroll
        for (int ni = 0; ni < 4; ni++){
            int col = warpN*32 + ni*8 + 2*(lane & 3);
            stage[r0*132 + col]       = acc[mi][ni][0];
            stage[r0*132 + col + 1]   = acc[mi][ni][1];
            stage[(r0+8)*132 + col]   = acc[mi][ni][2];
            stage[(r0+8)*132 + col+1] = acc[mi][ni][3];
        }
    }
    __syncthreads();

    for (int i = tid; i < 128 * 128; i += 256){
        int r = i >> 7, c = i & 127;
        float v = stage[r * 132 + c];
        int o = oBase + r; long long p = pBase + c;
        float bo = (o < rowSplit) ? biasa[o] : biasb[o - rowSplit];
        v += bo;
        long long off = (long long)bz * sY + (long long)o * P + p;
        if (EPI == 1){
            float gp = ep_g[(long long)bz * s_g + (long long)o * P + p];
            float xr = ep_x[(long long)bz * s_x + (long long)o * P + p];
            float g = 1.0f / (1.0f + expf(-gp));
            v = g * v + (1.0f - g) * xr;
        }
        Y[off] = v;
    }
}

// ================= split / transpose helpers =================
__global__ void convsplit(__nv_bfloat16* __restrict__ hi, __nv_bfloat16* __restrict__ lo,
                          const float* __restrict__ src, int n){
    int i = blockIdx.x * 256 + threadIdx.x;
    if (i < n){
        float v = src[i];
        __nv_bfloat16 h = __float2bfloat16(v);
        hi[i] = h;
        lo[i] = __float2bfloat16(v - __bfloat162float(h));
    }
}

// src[b][c][p] fp32  ->  out[b][p][Ktot] bf16 split at column offset kofs
__global__ void tsplit(const float* __restrict__ src, long long sb_,
                       __nv_bfloat16* __restrict__ hi, __nv_bfloat16* __restrict__ lo,
                       int Ktot, int kofs){
    __shared__ float t[32][33];
    int pb = blockIdx.x * 32, cb = blockIdx.y * 32, b = blockIdx.z;
    int tx = threadIdx.x & 31, ty = threadIdx.x >> 5;
    const float* s = src + (long long)b * sb_;
    for (int r = ty; r < 32; r += 8)
        t[r][tx] = s[(long long)(cb + r) * HW + pb + tx];
    __syncthreads();
    for (int i = ty; i < 32; i += 8){
        float v = t[tx][i];
        long long o = ((long long)b * HW + pb + i) * Ktot + kofs + cb + tx;
        __nv_bfloat16 h = __float2bfloat16(v);
        hi[o] = h;
        lo[o] = __float2bfloat16(v - __bfloat162float(h));
    }
}

// weighted reference -> transposed split into bt cols 640..1279
__global__ void wtsplit(__nv_bfloat16* __restrict__ hi, __nv_bfloat16* __restrict__ lo){
    __shared__ float t[32][33];
    int pb = blockIdx.x * 32, cb = blockIdx.y * 32, b = blockIdx.z;
    int tx = threadIdx.x & 31, ty = threadIdx.x >> 5;
    float a0 = g_attnw[b*2], a1 = g_attnw[b*2+1];
    const float* d0 = g_dec + (long long)g_attni[b*2]   * CC * HW;
    const float* d1 = g_dec + (long long)g_attni[b*2+1] * CC * HW;
    for (int r = ty; r < 32; r += 8){
        long long off = (long long)(cb + r) * HW + pb + tx;
        t[r][tx] = a0 * d0[off] + a1 * d1[off];
    }
    __syncthreads();
    for (int i = ty; i < 32; i += 8){
        float v = t[tx][i];
        long long o = ((long long)b * HW + pb + i) * (2*CC) + CC + cb + tx;
        __nv_bfloat16 h = __float2bfloat16(v);
        hi[o] = h;
        lo[o] = __float2bfloat16(v - __bfloat162float(h));
    }
}

// ---------------- generic tiled SGEMM (small/odd-shape GEMMs) ----------------
constexpr int GK = 16;

template<int TBM, int TBN, int EPI>
__global__ __launch_bounds__(256) void gemm_tpl(
    const float* __restrict__ Wa, const float* __restrict__ Wb, int rowSplit,
    const float* __restrict__ Xa, long long sXa,
    const float* __restrict__ Xb, long long sXb, int chanSplit,
    const float* __restrict__ biasa, const float* __restrict__ biasb,
    float* __restrict__ Y, long long sY,
    int M, int N, int K,
    float* __restrict__ ep_qp)
{
    constexpr int TM = TBM/16, TN = TBN/16;
    __shared__ float As[GK][TBM];
    __shared__ float Bs[GK][TBN];
    __shared__ float Red[TBM][17];

    const int tid = threadIdx.x;
    const int tx = tid & 15, ty = tid >> 4;
    const int pBase = blockIdx.x * TBN;
    const int oBase = blockIdx.y * TBM;
    const int bz = blockIdx.z;

    float acc[TM][TN];
#pragma unroll
    for (int i = 0; i < TM; i++)
#pragma unroll
        for (int j = 0; j < TN; j++) acc[i][j] = 0.f;

    for (int c0 = 0; c0 < K; c0 += GK){
#pragma unroll
        for (int l = 0; l < TBM/64; l++){
            int i = (tid >> 2) + l*64;
            int j4 = (tid & 3) << 2;
            int o = oBase + i;
            float4 w = make_float4(0.f,0.f,0.f,0.f);
            if (o < M){
                const float* wp = (o < rowSplit) ? (Wa + (long long)o*K)
                                                 : (Wb + (long long)(o-rowSplit)*K);
                w = *(const float4*)(wp + c0 + j4);
            }
            As[j4+0][i] = w.x; As[j4+1][i] = w.y; As[j4+2][i] = w.z; As[j4+3][i] = w.w;
        }
#pragma unroll
        for (int l = 0; l < TBN/64; l++){
            int j = tid >> 4;
            int n4 = ((tid & 15) << 2) + l*64;
            int c = c0 + j;
            const float* xp = (c < chanSplit) ? (Xa + bz*sXa + (long long)c*N)
                                              : (Xb + bz*sXb + (long long)(c - chanSplit)*N);
            *(float4*)&Bs[j][n4] = *(const float4*)(xp + pBase + n4);
        }
        __syncthreads();
#pragma unroll
        for (int kk = 0; kk < GK; kk++){
            float a[TM], b[TN];
#pragma unroll
            for (int i = 0; i < TM; i += 4){
                float4 t = *(const float4*)&As[kk][ty*TM + i];
                a[i]=t.x; a[i+1]=t.y; a[i+2]=t.z; a[i+3]=t.w;
            }
#pragma unroll
            for (int j = 0; j < TN; j += 4){
                float4 t = *(const float4*)&Bs[kk][tx*TN + j];
                b[j]=t.x; b[j+1]=t.y; b[j+2]=t.z; b[j+3]=t.w;
            }
#pragma unroll
            for (int i = 0; i < TM; i++)
#pragma unroll
                for (int j = 0; j < TN; j++)
                    acc[i][j] = fmaf(a[i], b[j], acc[i][j]);
        }
        __syncthreads();
    }

    if (EPI == 0){
#pragma unroll
        for (int i = 0; i < TM; i++){
            int o = oBase + ty*TM + i;
            if (o >= M) continue;
            float bo = (o < rowSplit) ? biasa[o] : biasb[o - rowSplit];
#pragma unroll
            for (int j = 0; j < TN; j += 4){
                float4 r = make_float4(acc[i][j]+bo, acc[i][j+1]+bo,
                                       acc[i][j+2]+bo, acc[i][j+3]+bo);
                *(float4*)(Y + bz*sY + (long long)o*N + pBase + tx*TN + j) = r;
            }
        }
    } else { // EPI == 2 : q projection (gelu + pixel reduce partial)
#pragma unroll
        for (int i = 0; i < TM; i++){
            int o = oBase + ty*TM + i;
            float s = 0.f;
            if (o < M){
                float bo = biasa[o];
#pragma unroll
                for (int j = 0; j < TN; j++) s += gelu_f(acc[i][j] + bo);
            }
            Red[ty*TM + i][tx] = s;
        }
        __syncthreads();
        if (tid < TBM){
            float s = 0.f;
#pragma unroll
            for (int t = 0; t < 16; t++) s += Red[tid][t];
            int o = oBase + tid;
            if (o < M)
                ep_qp[((bz*KDIM) + o)*64 + blockIdx.x] = s;
        }
    }
}

// ---------------- attention: q reduce, cosine sims, top-2, softmax ----------------
__global__ void attn_kernel(const float* __restrict__ mem_keys){
    __shared__ float qs[BB*KDIM];
    int tid = threadIdx.x;
    for (int idx = tid; idx < BB*KDIM; idx += 256){
        const float* p = g_qp + (long long)idx*64;
        float s = 0.f;
        for (int t = 0; t < 64; t++) s += p[t];
        qs[idx] = s * (1.0f/4096.0f);
    }
    __syncthreads();
    if (tid < BB){
        int b = tid;
        const float* q = qs + b*KDIM;
        float qn = 0.f;
        for (int j = 0; j < KDIM; j++) qn += q[j]*q[j];
        qn = fmaxf(sqrtf(qn), 1e-12f);
        float v[MR];
        for (int m = 0; m < MR; m++){
            const float* kk = mem_keys + m*KDIM;
            float kn = 0.f, d = 0.f;
            for (int j = 0; j < KDIM; j++){ kn += kk[j]*kk[j]; d += q[j]*kk[j]; }
            kn = fmaxf(sqrtf(kn), 1e-12f);
            v[m] = d/(qn*kn);
        }
        int i0 = 0;
        for (int m = 1; m < MR; m++) if (v[m] > v[i0]) i0 = m;
        int i1 = -1;
        for (int m = 0; m < MR; m++){
            if (m == i0) continue;
            if (i1 < 0 || v[m] > v[i1]) i1 = m;
        }
        float e1 = expf((v[i1]-v[i0])*10.0f);
        float a0 = 1.0f/(1.0f+e1);
        float a1 = e1/(1.0f+e1);
        g_attnw[b*2] = a0; g_attnw[b*2+1] = a1;
        g_attni[b*2] = i0; g_attni[b*2+1] = i1;
    }
}

// ---------------- bilinear 8->64 upsample + gelu + depthwise 3x3 ----------------
__global__ __launch_bounds__(256) void up_gelu_dw(
    const float* __restrict__ wdw, const float* __restrict__ bdw)
{
    int m = blockIdx.x / CC, c = blockIdx.x % CC;
    __shared__ float sm[64][65];
    __shared__ float tt[64];
    int tid = threadIdx.x;
    if (tid < 64) tt[tid] = g_t[((long long)m*CC + c)*64 + tid];
    __syncthreads();
    for (int i = tid; i < 1024; i += 256){
        int p = i << 2, h = p >> 6, w0 = p & 63;
        float shf = h*0.125f - 0.4375f;
        int ih = (int)floorf(shf);
        float fh = shf - (float)ih;
        int h0 = ih < 0 ? 0 : ih;
        int h1 = (ih+1 > 7) ? 7 : ih+1;
#pragma unroll
        for (int q2 = 0; q2 < 4; q2++){
            int w = w0 + q2;
            float swf = w*0.125f - 0.4375f;
            int iw = (int)floorf(swf);
            float fw = swf - (float)iw;
            int wA = iw < 0 ? 0 : iw;
            int wB = (iw+1 > 7) ? 7 : iw+1;
            float top = (1.f-fw)*tt[h0*8+wA] + fw*tt[h0*8+wB];
            float bot = (1.f-fw)*tt[h1*8+wA] + fw*tt[h1*8+wB];
            float v = (1.f-fh)*top + fh*bot;
            sm[h][w] = gelu_f(v);
        }
    }
    __syncthreads();
    float w9[9];
#pragma unroll
    for (int t = 0; t < 9; t++) w9[t] = wdw[c*9+t];
    float bb = bdw[c];
    float* dst = g_dec + ((long long)m*CC + c)*HW;
    for (int i = tid; i < 1024; i += 256){
        int p = i << 2, h = p >> 6, w0 = p & 63;
        float ov[4];
#pragma unroll
        for (int q2 = 0; q2 < 4; q2++){
            int w = w0 + q2;
            float s = bb;
#pragma unroll
            for (int ky = 0; ky < 3; ky++){
                int hh = h + ky - 1;
                if ((unsigned)hh > 63u) continue;
#pragma unroll
                for (int kx = 0; kx < 3; kx++){
                    int ww = w + kx - 1;
                    if ((unsigned)ww > 63u) continue;
                    s = fmaf(w9[ky*3+kx], sm[hh][ww], s);
                }
            }
            ov[q2] = s;
        }
        *(float4*)(dst + p) = make_float4(ov[0], ov[1], ov[2], ov[3]);
    }
}

// ---------------- group-norm statistics ----------------
__global__ void gn_stats(){
    int b = blockIdx.x >> 5, g = blockIdx.x & 31;
    int tid = threadIdx.x;
    const float4* p = (const float4*)(g_big + ((long long)b*2*CC + g*CPG)*HW);
    const int n4 = CPG*HW/4;
    float s = 0.f, ss = 0.f;
    for (int i = tid; i < n4; i += 256){
        float4 v = p[i];
        s  += v.x + v.y + v.z + v.w;
        ss += v.x*v.x + v.y*v.y + v.z*v.z + v.w*v.w;
    }
    __shared__ float sh1[256], sh2[256];
    sh1[tid] = s; sh2[tid] = ss;
    __syncthreads();
    for (int st = 128; st > 0; st >>= 1){
        if (tid < st){ sh1[tid] += sh1[tid+st]; sh2[tid] += sh2[tid+st]; }
        __syncthreads();
    }
    if (tid == 0){
        const float inv = 1.0f/(CPG*HW);
        float mu = sh1[0]*inv;
        float var = sh2[0]*inv - mu*mu;
        g_gn[blockIdx.x*2]   = mu;
        g_gn[blockIdx.x*2+1] = rsqrtf(var + 1e-5f);
    }
}

// ---------------- group-norm + gelu + depthwise 3x3 ----------------
__global__ __launch_bounds__(256) void gn_gelu_dw(
    const float* __restrict__ gamma, const float* __restrict__ beta,
    const float* __restrict__ wdw, const float* __restrict__ bdw)
{
    int b = blockIdx.x / CC, c = blockIdx.x % CC;
    __shared__ float sm[64][65];
    int tid = threadIdx.x;
    const float* src = g_big + ((long long)b*2*CC + c)*HW;
    int g = c / CPG;
    float mu = g_gn[(b*GROUPS+g)*2], rs = g_gn[(b*GROUPS+g)*2+1];
    float ga = gamma[c]*rs;
    float be = beta[c] - mu*ga;
    for (int i = tid; i < 1024; i += 256){
        float4 v = ((const float4*)src)[i];
        int p = i << 2, h = p >> 6, w0 = p & 63;
        sm[h][w0]   = gelu_f(v.x*ga + be);
        sm[h][w0+1] = gelu_f(v.y*ga + be);
        sm[h][w0+2] = gelu_f(v.z*ga + be);
        sm[h][w0+3] = gelu_f(v.w*ga + be);
    }
    __syncthreads();
    float w9[9];
#pragma unroll
    for (int t = 0; t < 9; t++) w9[t] = wdw[c*9+t];
    float bb = bdw[c];
    float* dst = g_f2 + ((long long)b*CC + c)*HW;
    for (int i = tid; i < 1024; i += 256){
        int p = i << 2, h = p >> 6, w0 = p & 63;
        float ov[4];
#pragma unroll
        for (int q2 = 0; q2 < 4; q2++){
            int w = w0 + q2;
            float s = bb;
#pragma unroll
            for (int ky = 0; ky < 3; ky++){
                int hh = h + ky - 1;
                if ((unsigned)hh > 63u) continue;
#pragma unroll
                for (int kx = 0; kx < 3; kx++){
                    int ww = w + kx - 1;
                    if ((unsigned)ww > 63u) continue;
                    s = fmaf(w9[ky*3+kx], sm[hh][ww], s);
                }
            }
            ov[q2] = s;
        }
        *(float4*)(dst + p) = make_float4(ov[0], ov[1], ov[2], ov[3]);
    }
}

// ---------------- host launcher ----------------
extern "C" void kernel_launch(void* const* d_in, const int* in_sizes, int n_in,
                              void* d_out, int out_size)
{
    const float* x         = (const float*)d_in[0];
    const float* qp_w      = (const float*)d_in[1];
    const float* qp_b      = (const float*)d_in[2];
    const float* mem_keys  = (const float*)d_in[3];
    const float* mem_values= (const float*)d_in[4];
    const float* vd_w1     = (const float*)d_in[5];
    const float* vd_b1     = (const float*)d_in[6];
    const float* vd_wdw    = (const float*)d_in[7];
    const float* vd_bdw    = (const float*)d_in[8];
    const float* fn_w1     = (const float*)d_in[9];
    const float* fn_b1     = (const float*)d_in[10];
    const float* fn_gamma  = (const float*)d_in[11];
    const float* fn_beta   = (const float*)d_in[12];
    const float* fn_wdw    = (const float*)d_in[13];
    const float* fn_bdw    = (const float*)d_in[14];
    const float* fn_w2     = (const float*)d_in[15];
    const float* fn_b2     = (const float*)d_in[16];
    const float* fg_w      = (const float*)d_in[17];
    const float* fg_b      = (const float*)d_in[18];
    float* out = (float*)d_out;
    (void)in_sizes; (void)n_in; (void)out_size;

    float *p_t, *p_big, *p_f2, *p_qp;
    __nv_bfloat16 *p_whi, *p_wlo, *p_w2hi, *p_w2lo, *p_bthi, *p_btlo, *p_fthi, *p_ftlo;
    cudaGetSymbolAddress((void**)&p_t,    g_t);
    cudaGetSymbolAddress((void**)&p_big,  g_big);
    cudaGetSymbolAddress((void**)&p_f2,   g_f2);
    cudaGetSymbolAddress((void**)&p_qp,   g_qp);
    cudaGetSymbolAddress((void**)&p_whi,  g_whi);
    cudaGetSymbolAddress((void**)&p_wlo,  g_wlo);
    cudaGetSymbolAddress((void**)&p_w2hi, g_w2hi);
    cudaGetSymbolAddress((void**)&p_w2lo, g_w2lo);
    cudaGetSymbolAddress((void**)&p_bthi, g_bthi);
    cudaGetSymbolAddress((void**)&p_btlo, g_btlo);
    cudaGetSymbolAddress((void**)&p_fthi, g_fthi);
    cudaGetSymbolAddress((void**)&p_ftlo, g_ftlo);

    const int DSM = 2 * STAGE_B;   // 81920: 2-stage operands; epilogue stage (67584) overlaps
    cudaFuncSetAttribute(gemm_tc<0>, cudaFuncAttributeMaxDynamicSharedMemorySize, DSM);
    cudaFuncSetAttribute(gemm_tc<1>, cudaFuncAttributeMaxDynamicSharedMemorySize, DSM);

    const long long sX = (long long)CC*HW;

    // 0) weight conversions (bf16 split)
    convsplit<<<(CC*2*CC+255)/256,256>>>(p_whi,            p_wlo,            fn_w1, CC*2*CC);
    convsplit<<<(CC*2*CC+255)/256,256>>>(p_whi + CC*2*CC,  p_wlo + CC*2*CC,  fg_w,  CC*2*CC);
    convsplit<<<(CC*CC+255)/256,256>>>(p_w2hi, p_w2lo, fn_w2, CC*CC);

    // 1) t[m] = vd_w1 @ mem_values[m] + vd_b1 (at 8x8 resolution)
    gemm_tpl<64,64,0><<<dim3(1,10,MR),256>>>(
        vd_w1, vd_w1, CC,
        mem_values, (long long)CC*64, mem_values, (long long)CC*64, CC,
        vd_b1, vd_b1,
        p_t, (long long)CC*64,
        CC, 64, CC, nullptr);

    // 2) q-projection partials
    gemm_tpl<64,64,2><<<dim3(64,3,BB),256>>>(
        qp_w, qp_w, KDIM,
        x, sX, x, sX, CC,
        qp_b, qp_b,
        nullptr, 0,
        KDIM, HW, CC, p_qp);

    // 3) cosine attention, top-2, softmax
    attn_kernel<<<1,256>>>(mem_keys);

    // 4) upsample + gelu + depthwise per memory row
    up_gelu_dw<<<MR*CC,256>>>(vd_wdw, vd_bdw);

    // 5) B operand build: x and weighted-ref, transposed + bf16 split
    tsplit<<<dim3(HW/32, CC/32, BB),256>>>(x, sX, p_bthi, p_btlo, 2*CC, 0);
    wtsplit<<<dim3(HW/32, CC/32, BB),256>>>(p_bthi, p_btlo);

    // 6) fused fn1 + gate GEMM (mma.sync bf16 split)
    gemm_tc<0><<<dim3(32,10,BB),256,DSM>>>(
        p_whi, p_wlo, p_bthi, p_btlo,
        fn_b1, fg_b, CC,
        p_big, (long long)2*CC*HW, 2*CC,
        nullptr, 0, nullptr, 0);

    // 7) group-norm stats
    gn_stats<<<BB*GROUPS,256>>>();

    // 8) gn + gelu + depthwise
    gn_gelu_dw<<<BB*CC,256>>>(fn_gamma, fn_beta, fn_wdw, fn_bdw);

    // 9) f2 transpose + split
    tsplit<<<dim3(HW/32, CC/32, BB),256>>>(p_f2, sX, p_fthi, p_ftlo, CC, 0);

    // 10) fn2 GEMM + sigmoid-gate blend (mma.sync bf16 split)
    gemm_tc<1><<<dim3(32,5,BB),256,DSM>>>(
        p_w2hi, p_w2lo, p_fthi, p_ftlo,
        fn_b2, fn_b2, CC,
        out, (long long)CC*HW, CC,
        p_big + (long long)CC*HW, (long long)2*CC*HW,
        x, sX);
}

// round 5
// speedup vs baseline: 2.0546x; 1.2853x over previous
#include <cuda_runtime.h>
#include <cuda_bf16.h>
#include <math.h>
#include <stdint.h>

// ---------------- problem constants ----------------
#define BB 8
#define CC 640
#define HW 4096     // 64*64
#define KDIM 160
#define MR 4
#define GROUPS 32
#define CPG 20      // 640/32
#define QT 32       // qp partial tiles

// ---------------- scratch (device globals; no allocs allowed) ----------------
__device__ float g_t   [MR*CC*64];
__device__ float g_dec [MR*CC*HW];
__device__ float g_big [BB*2*CC*HW];
__device__ float g_f2  [BB*CC*HW];
__device__ float g_qp  [BB*KDIM*QT];
__device__ float g_gn  [BB*GROUPS*2];
__device__ float g_attnw[BB*2];
__device__ int   g_attni[BB*2];

// bf16 split operands for tensor-core GEMMs
__device__ __nv_bfloat16 g_whi [2*CC*2*CC];
__device__ __nv_bfloat16 g_wlo [2*CC*2*CC];
__device__ __nv_bfloat16 g_w2hi[CC*CC];
__device__ __nv_bfloat16 g_w2lo[CC*CC];
__device__ __nv_bfloat16 g_qphi[256*CC];     // qp_w zero-padded to 256 rows
__device__ __nv_bfloat16 g_qplo[256*CC];
__device__ __nv_bfloat16 g_bthi[(long long)BB*HW*2*CC];
__device__ __nv_bfloat16 g_btlo[(long long)BB*HW*2*CC];
__device__ __nv_bfloat16 g_fthi[(long long)BB*HW*CC];
__device__ __nv_bfloat16 g_ftlo[(long long)BB*HW*CC];

__device__ __forceinline__ float gelu_f(float v){
    return 0.5f*v*(1.0f + erff(v*0.70710678118654752f));
}

// ================= mma.sync helpers (sm_80+ base ISA) =================
__device__ __forceinline__ uint32_t smem_u32(const void* p){
    uint32_t a;
    asm("{ .reg .u64 t; cvta.to.shared.u64 t, %1; cvt.u32.u64 %0, t; }" : "=r"(a) : "l"(p));
    return a;
}
__device__ __forceinline__ void cpa16(uint32_t dst, const void* src){
    asm volatile("cp.async.cg.shared.global [%0], [%1], 16;" :: "r"(dst), "l"(src));
}
__device__ __forceinline__ void ldm_x4(uint32_t (&r)[4], uint32_t addr){
    asm volatile("ldmatrix.sync.aligned.m8n8.x4.shared.b16 {%0,%1,%2,%3}, [%4];"
        : "=r"(r[0]),"=r"(r[1]),"=r"(r[2]),"=r"(r[3]) : "r"(addr));
}
__device__ __forceinline__ void ldm_x2(uint32_t (&r)[2], uint32_t addr){
    asm volatile("ldmatrix.sync.aligned.m8n8.x2.shared.b16 {%0,%1}, [%2];"
        : "=r"(r[0]),"=r"(r[1]) : "r"(addr));
}
__device__ __forceinline__ void mma_bf16(float (&d)[4], const uint32_t (&a)[4], const uint32_t (&b)[2]){
    asm volatile("mma.sync.aligned.m16n8k16.row.col.f32.bf16.bf16.f32 "
        "{%0,%1,%2,%3}, {%4,%5,%6,%7}, {%8,%9}, {%0,%1,%2,%3};"
        : "+f"(d[0]),"+f"(d[1]),"+f"(d[2]),"+f"(d[3])
        : "r"(a[0]),"r"(a[1]),"r"(a[2]),"r"(a[3]), "r"(b[0]),"r"(b[1]));
}

// ================= split-bf16 tensor-core GEMM (mma.sync) =================
// Y[bz, o, p] = sum_k W[o,k] * B[bz, p, k] (+bias), W = Whi+Wlo, B = Bhi+Blo.
// CTA tile 128(M) x 128(N), K-chunks of 32, 2-stage cp.async pipeline.
// EPI 0: plain store; 1: sigmoid-gate blend; 2: gelu + pixel-reduce (q projection).
#define KC 32
#define TPITCH 80           // bytes per smem tile row (64 data + 16 pad)
#define TILE_B (128*TPITCH) // 10240
#define STAGE_B (4*TILE_B)  // 40960

template<int EPI>
__global__ void __launch_bounds__(256,2) gemm_tc(
    const __nv_bfloat16* __restrict__ Whi, const __nv_bfloat16* __restrict__ Wlo,
    long long sA,
    const __nv_bfloat16* __restrict__ Bhi, const __nv_bfloat16* __restrict__ Blo,
    long long sB,
    const float* __restrict__ biasa, const float* __restrict__ biasb, int rowSplit,
    float* __restrict__ Y, long long sY, int Kiter,
    const float* __restrict__ ep_g, long long s_g,
    const float* __restrict__ ep_x, long long s_x,
    float* __restrict__ ep_qp)
{
    extern __shared__ char smem[];
    const uint32_t sb = smem_u32(smem);
    const int tid = threadIdx.x, wid = tid >> 5, lane = tid & 31;
    const int warpM = wid >> 2, warpN = wid & 3;
    const int pBase = blockIdx.x * 128, oBase = blockIdx.y * 128, bz = blockIdx.z;
    const long long P = 4096;

    const __nv_bfloat16* ah_g = Whi + (long long)oBase * sA;
    const __nv_bfloat16* al_g = Wlo + (long long)oBase * sA;
    const __nv_bfloat16* bh_g = Bhi + ((long long)bz * P + pBase) * sB;
    const __nv_bfloat16* bl_g = Blo + ((long long)bz * P + pBase) * sB;

    float acc[4][4][4];
#pragma unroll
    for (int a = 0; a < 4; a++)
#pragma unroll
        for (int b = 0; b < 4; b++)
#pragma unroll
            for (int c = 0; c < 4; c++) acc[a][b][c] = 0.f;

    const uint32_t aoff = (uint32_t)((warpM*64 + (lane & 15)) * TPITCH + (lane >> 4) * 16);
    const uint32_t boff = (uint32_t)((warpN*32 + (lane & 7)) * TPITCH + ((lane >> 3) & 1) * 16);

    const int nCh = Kiter / KC;

    auto load_stage = [&](int st, int c0){
        uint32_t base = sb + st * STAGE_B;
#pragma unroll
        for (int i = 0; i < 8; i++){
            int t = tid + (i << 8);
            int tile = t >> 9, u = t & 511, r = u >> 2, ck = u & 3;
            uint32_t dst = base + tile*TILE_B + (uint32_t)(r*TPITCH + ck*16);
            const __nv_bfloat16* gsrc;
            long long stride;
            if      (tile == 0){ gsrc = ah_g; stride = sA; }
            else if (tile == 1){ gsrc = al_g; stride = sA; }
            else if (tile == 2){ gsrc = bh_g; stride = sB; }
            else               { gsrc = bl_g; stride = sB; }
            cpa16(dst, gsrc + (long long)r * stride + c0 + (ck << 3));
        }
        asm volatile("cp.async.commit_group;" ::: "memory");
    };

    load_stage(0, 0);

    for (int ch = 0; ch < nCh; ch++){
        if (ch + 1 < nCh){
            load_stage((ch + 1) & 1, (ch + 1) * KC);
            asm volatile("cp.async.wait_group 1;" ::: "memory");
        } else {
            asm volatile("cp.async.wait_group 0;" ::: "memory");
        }
        __syncthreads();

        uint32_t base = sb + (ch & 1) * STAGE_B;
        uint32_t SAH = base, SAL = base + TILE_B, SBH = base + 2*TILE_B, SBL = base + 3*TILE_B;
#pragma unroll
        for (int ks = 0; ks < 2; ks++){
            uint32_t ko = ks * 32;   // 16 bf16 = 32 bytes
            uint32_t bh[4][2], bl[4][2];
#pragma unroll
            for (int ni = 0; ni < 4; ni++){
                ldm_x2(bh[ni], SBH + boff + ni*8*TPITCH + ko);
                ldm_x2(bl[ni], SBL + boff + ni*8*TPITCH + ko);
            }
            // streams A fragments to keep live registers low (2 CTAs/SM)
#pragma unroll
            for (int mi = 0; mi < 4; mi++){
                uint32_t a[4];
                ldm_x4(a, SAH + aoff + mi*16*TPITCH + ko);
#pragma unroll
                for (int ni = 0; ni < 4; ni++) mma_bf16(acc[mi][ni], a, bh[ni]);
#pragma unroll
                for (int ni = 0; ni < 4; ni++) mma_bf16(acc[mi][ni], a, bl[ni]);
            }
#pragma unroll
            for (int mi = 0; mi < 4; mi++){
                uint32_t a[4];
                ldm_x4(a, SAL + aoff + mi*16*TPITCH + ko);
#pragma unroll
                for (int ni = 0; ni < 4; ni++) mma_bf16(acc[mi][ni], a, bh[ni]);
            }
        }
        __syncthreads();
    }

    // ---- epilogue: acc -> SMEM stage (pitch 132) -> coalesced out ----
    float* stage = (float*)smem;
#pragma unroll
    for (int mi = 0; mi < 4; mi++){
        int r0 = warpM*64 + mi*16 + (lane >> 2);
#pragma unroll
        for (int ni = 0; ni < 4; ni++){
            int col = warpN*32 + ni*8 + 2*(lane & 3);
            stage[r0*132 + col]       = acc[mi][ni][0];
            stage[r0*132 + col + 1]   = acc[mi][ni][1];
            stage[(r0+8)*132 + col]   = acc[mi][ni][2];
            stage[(r0+8)*132 + col+1] = acc[mi][ni][3];
        }
    }
    __syncthreads();

    if (EPI == 2){
        // q projection: per-row gelu(v + bias) summed over 128 pixels
        int r = tid >> 1, h = tid & 1;
        int o = oBase + r;
        float s = 0.f;
        if (o < KDIM){
            float bo = biasa[o];
            const float* row = stage + r * 132 + h * 64;
#pragma unroll 8
            for (int j = 0; j < 64; j++) s += gelu_f(row[j] + bo);
        }
        s += __shfl_xor_sync(0xffffffffu, s, 1);
        if (h == 0 && o < KDIM)
            ep_qp[((bz*KDIM) + o)*QT + blockIdx.x] = s;
        return;
    }

    for (int i = tid; i < 128 * 128; i += 256){
        int r = i >> 7, c = i & 127;
        float v = stage[r * 132 + c];
        int o = oBase + r; long long p = pBase + c;
        float bo = (o < rowSplit) ? biasa[o] : biasb[o - rowSplit];
        v += bo;
        long long off = (long long)bz * sY + (long long)o * P + p;
        if (EPI == 1){
            float gp = ep_g[(long long)bz * s_g + (long long)o * P + p];
            float xr = ep_x[(long long)bz * s_x + (long long)o * P + p];
            float g = 1.0f / (1.0f + expf(-gp));
            v = g * v + (1.0f - g) * xr;
        }
        Y[off] = v;
    }
}

// ================= split / transpose helpers =================
__global__ void convsplit(__nv_bfloat16* __restrict__ hi, __nv_bfloat16* __restrict__ lo,
                          const float* __restrict__ src, int n){
    int i = blockIdx.x * 256 + threadIdx.x;
    if (i < n){
        float v = src[i];
        __nv_bfloat16 h = __float2bfloat16(v);
        hi[i] = h;
        lo[i] = __float2bfloat16(v - __bfloat162float(h));
    }
}

// qp_w [160][640] -> zero-padded [256][640] bf16 split
__global__ void qpsplit(__nv_bfloat16* __restrict__ hi, __nv_bfloat16* __restrict__ lo,
                        const float* __restrict__ w){
    int i = blockIdx.x * 256 + threadIdx.x;
    if (i < 256*CC){
        float v = (i < KDIM*CC) ? w[i] : 0.f;
        __nv_bfloat16 h = __float2bfloat16(v);
        hi[i] = h;
        lo[i] = __float2bfloat16(v - __bfloat162float(h));
    }
}

// src[b][c][p] fp32  ->  out[b][p][Ktot] bf16 split at column offset kofs
__global__ void tsplit(const float* __restrict__ src, long long sb_,
                       __nv_bfloat16* __restrict__ hi, __nv_bfloat16* __restrict__ lo,
                       int Ktot, int kofs){
    __shared__ float t[32][33];
    int pb = blockIdx.x * 32, cb = blockIdx.y * 32, b = blockIdx.z;
    int tx = threadIdx.x & 31, ty = threadIdx.x >> 5;
    const float* s = src + (long long)b * sb_;
    for (int r = ty; r < 32; r += 8)
        t[r][tx] = s[(long long)(cb + r) * HW + pb + tx];
    __syncthreads();
    for (int i = ty; i < 32; i += 8){
        float v = t[tx][i];
        long long o = ((long long)b * HW + pb + i) * Ktot + kofs + cb + tx;
        __nv_bfloat16 h = __float2bfloat16(v);
        hi[o] = h;
        lo[o] = __float2bfloat16(v - __bfloat162float(h));
    }
}

// weighted reference -> transposed split into bt cols 640..1279
__global__ void wtsplit(__nv_bfloat16* __restrict__ hi, __nv_bfloat16* __restrict__ lo){
    __shared__ float t[32][33];
    int pb = blockIdx.x * 32, cb = blockIdx.y * 32, b = blockIdx.z;
    int tx = threadIdx.x & 31, ty = threadIdx.x >> 5;
    float a0 = g_attnw[b*2], a1 = g_attnw[b*2+1];
    const float* d0 = g_dec + (long long)g_attni[b*2]   * CC * HW;
    const float* d1 = g_dec + (long long)g_attni[b*2+1] * CC * HW;
    for (int r = ty; r < 32; r += 8){
        long long off = (long long)(cb + r) * HW + pb + tx;
        t[r][tx] = a0 * d0[off] + a1 * d1[off];
    }
    __syncthreads();
    for (int i = ty; i < 32; i += 8){
        float v = t[tx][i];
        long long o = ((long long)b * HW + pb + i) * (2*CC) + CC + cb + tx;
        __nv_bfloat16 h = __float2bfloat16(v);
        hi[o] = h;
        lo[o] = __float2bfloat16(v - __bfloat162float(h));
    }
}

// ---------------- generic tiled SGEMM (small/odd-shape GEMMs) ----------------
constexpr int GK = 16;

template<int TBM, int TBN>
__global__ __launch_bounds__(256) void gemm_tpl(
    const float* __restrict__ Wa, int rowSplit,
    const float* __restrict__ Xa, long long sXa,
    const float* __restrict__ biasa,
    float* __restrict__ Y, long long sY,
    int M, int N, int K)
{
    constexpr int TM = TBM/16, TN = TBN/16;
    __shared__ float As[GK][TBM];
    __shared__ float Bs[GK][TBN];

    const int tid = threadIdx.x;
    const int tx = tid & 15, ty = tid >> 4;
    const int pBase = blockIdx.x * TBN;
    const int oBase = blockIdx.y * TBM;
    const int bz = blockIdx.z;

    float acc[TM][TN];
#pragma unroll
    for (int i = 0; i < TM; i++)
#pragma unroll
        for (int j = 0; j < TN; j++) acc[i][j] = 0.f;

    for (int c0 = 0; c0 < K; c0 += GK){
#pragma unroll
        for (int l = 0; l < TBM/64; l++){
            int i = (tid >> 2) + l*64;
            int j4 = (tid & 3) << 2;
            int o = oBase + i;
            float4 w = make_float4(0.f,0.f,0.f,0.f);
            if (o < M) w = *(const float4*)(Wa + (long long)o*K + c0 + j4);
            As[j4+0][i] = w.x; As[j4+1][i] = w.y; As[j4+2][i] = w.z; As[j4+3][i] = w.w;
        }
#pragma unroll
        for (int l = 0; l < TBN/64; l++){
            int j = tid >> 4;
            int n4 = ((tid & 15) << 2) + l*64;
            int c = c0 + j;
            const float* xp = Xa + bz*sXa + (long long)c*N;
            *(float4*)&Bs[j][n4] = *(const float4*)(xp + pBase + n4);
        }
        __syncthreads();
#pragma unroll
        for (int kk = 0; kk < GK; kk++){
            float a[TM], b[TN];
#pragma unroll
            for (int i = 0; i < TM; i += 4){
                float4 t = *(const float4*)&As[kk][ty*TM + i];
                a[i]=t.x; a[i+1]=t.y; a[i+2]=t.z; a[i+3]=t.w;
            }
#pragma unroll
            for (int j = 0; j < TN; j += 4){
                float4 t = *(const float4*)&Bs[kk][tx*TN + j];
                b[j]=t.x; b[j+1]=t.y; b[j+2]=t.z; b[j+3]=t.w;
            }
#pragma unroll
            for (int i = 0; i < TM; i++)
#pragma unroll
                for (int j = 0; j < TN; j++)
                    acc[i][j] = fmaf(a[i], b[j], acc[i][j]);
        }
        __syncthreads();
    }

#pragma unroll
    for (int i = 0; i < TM; i++){
        int o = oBase + ty*TM + i;
        if (o >= M) continue;
        float bo = biasa[o];
#pragma unroll
        for (int j = 0; j < TN; j += 4){
            float4 r = make_float4(acc[i][j]+bo, acc[i][j+1]+bo,
                                   acc[i][j+2]+bo, acc[i][j+3]+bo);
            *(float4*)(Y + bz*sY + (long long)o*N + pBase + tx*TN + j) = r;
        }
    }
}

// ---------------- attention: q reduce, cosine sims, top-2, softmax ----------------
__global__ void attn_kernel(const float* __restrict__ mem_keys){
    __shared__ float qs[BB*KDIM];
    int tid = threadIdx.x;
    for (int idx = tid; idx < BB*KDIM; idx += 256){
        const float* p = g_qp + (long long)idx*QT;
        float s = 0.f;
        for (int t = 0; t < QT; t++) s += p[t];
        qs[idx] = s * (1.0f/4096.0f);
    }
    __syncthreads();
    if (tid < BB){
        int b = tid;
        const float* q = qs + b*KDIM;
        float qn = 0.f;
        for (int j = 0; j < KDIM; j++) qn += q[j]*q[j];
        qn = fmaxf(sqrtf(qn), 1e-12f);
        float v[MR];
        for (int m = 0; m < MR; m++){
            const float* kk = mem_keys + m*KDIM;
            float kn = 0.f, d = 0.f;
            for (int j = 0; j < KDIM; j++){ kn += kk[j]*kk[j]; d += q[j]*kk[j]; }
            kn = fmaxf(sqrtf(kn), 1e-12f);
            v[m] = d/(qn*kn);
        }
        int i0 = 0;
        for (int m = 1; m < MR; m++) if (v[m] > v[i0]) i0 = m;
        int i1 = -1;
        for (int m = 0; m < MR; m++){
            if (m == i0) continue;
            if (i1 < 0 || v[m] > v[i1]) i1 = m;
        }
        float e1 = expf((v[i1]-v[i0])*10.0f);
        float a0 = 1.0f/(1.0f+e1);
        float a1 = e1/(1.0f+e1);
        g_attnw[b*2] = a0; g_attnw[b*2+1] = a1;
        g_attni[b*2] = i0; g_attni[b*2+1] = i1;
    }
}

// ---------------- bilinear 8->64 upsample + gelu + depthwise 3x3 ----------------
__global__ __launch_bounds__(256) void up_gelu_dw(
    const float* __restrict__ wdw, const float* __restrict__ bdw)
{
    int m = blockIdx.x / CC, c = blockIdx.x % CC;
    __shared__ float sm[64][65];
    __shared__ float tt[64];
    int tid = threadIdx.x;
    if (tid < 64) tt[tid] = g_t[((long long)m*CC + c)*64 + tid];
    __syncthreads();
    for (int i = tid; i < 1024; i += 256){
        int p = i << 2, h = p >> 6, w0 = p & 63;
        float shf = h*0.125f - 0.4375f;
        int ih = (int)floorf(shf);
        float fh = shf - (float)ih;
        int h0 = ih < 0 ? 0 : ih;
        int h1 = (ih+1 > 7) ? 7 : ih+1;
#pragma unroll
        for (int q2 = 0; q2 < 4; q2++){
            int w = w0 + q2;
            float swf = w*0.125f - 0.4375f;
            int iw = (int)floorf(swf);
            float fw = swf - (float)iw;
            int wA = iw < 0 ? 0 : iw;
            int wB = (iw+1 > 7) ? 7 : iw+1;
            float top = (1.f-fw)*tt[h0*8+wA] + fw*tt[h0*8+wB];
            float bot = (1.f-fw)*tt[h1*8+wA] + fw*tt[h1*8+wB];
            float v = (1.f-fh)*top + fh*bot;
            sm[h][w] = gelu_f(v);
        }
    }
    __syncthreads();
    float w9[9];
#pragma unroll
    for (int t = 0; t < 9; t++) w9[t] = wdw[c*9+t];
    float bb = bdw[c];
    float* dst = g_dec + ((long long)m*CC + c)*HW;
    for (int i = tid; i < 1024; i += 256){
        int p = i << 2, h = p >> 6, w0 = p & 63;
        float ov[4];
#pragma unroll
        for (int q2 = 0; q2 < 4; q2++){
            int w = w0 + q2;
            float s = bb;
#pragma unroll
            for (int ky = 0; ky < 3; ky++){
                int hh = h + ky - 1;
                if ((unsigned)hh > 63u) continue;
#pragma unroll
                for (int kx = 0; kx < 3; kx++){
                    int ww = w + kx - 1;
                    if ((unsigned)ww > 63u) continue;
                    s = fmaf(w9[ky*3+kx], sm[hh][ww], s);
                }
            }
            ov[q2] = s;
        }
        *(float4*)(dst + p) = make_float4(ov[0], ov[1], ov[2], ov[3]);
    }
}

// ---------------- group-norm statistics ----------------
__global__ void gn_stats(){
    int b = blockIdx.x >> 5, g = blockIdx.x & 31;
    int tid = threadIdx.x;
    const float4* p = (const float4*)(g_big + ((long long)b*2*CC + g*CPG)*HW);
    const int n4 = CPG*HW/4;
    float s = 0.f, ss = 0.f;
    for (int i = tid; i < n4; i += 256){
        float4 v = p[i];
        s  += v.x + v.y + v.z + v.w;
        ss += v.x*v.x + v.y*v.y + v.z*v.z + v.w*v.w;
    }
    __shared__ float sh1[256], sh2[256];
    sh1[tid] = s; sh2[tid] = ss;
    __syncthreads();
    for (int st = 128; st > 0; st >>= 1){
        if (tid < st){ sh1[tid] += sh1[tid+st]; sh2[tid] += sh2[tid+st]; }
        __syncthreads();
    }
    if (tid == 0){
        const float inv = 1.0f/(CPG*HW);
        float mu = sh1[0]*inv;
        float var = sh2[0]*inv - mu*mu;
        g_gn[blockIdx.x*2]   = mu;
        g_gn[blockIdx.x*2+1] = rsqrtf(var + 1e-5f);
    }
}

// ---------------- group-norm + gelu + depthwise 3x3 ----------------
__global__ __launch_bounds__(256) void gn_gelu_dw(
    const float* __restrict__ gamma, const float* __restrict__ beta,
    const float* __restrict__ wdw, const float* __restrict__ bdw)
{
    int b = blockIdx.x / CC, c = blockIdx.x % CC;
    __shared__ float sm[64][65];
    int tid = threadIdx.x;
    const float* src = g_big + ((long long)b*2*CC + c)*HW;
    int g = c / CPG;
    float mu = g_gn[(b*GROUPS+g)*2], rs = g_gn[(b*GROUPS+g)*2+1];
    float ga = gamma[c]*rs;
    float be = beta[c] - mu*ga;
    for (int i = tid; i < 1024; i += 256){
        float4 v = ((const float4*)src)[i];
        int p = i << 2, h = p >> 6, w0 = p & 63;
        sm[h][w0]   = gelu_f(v.x*ga + be);
        sm[h][w0+1] = gelu_f(v.y*ga + be);
        sm[h][w0+2] = gelu_f(v.z*ga + be);
        sm[h][w0+3] = gelu_f(v.w*ga + be);
    }
    __syncthreads();
    float w9[9];
#pragma unroll
    for (int t = 0; t < 9; t++) w9[t] = wdw[c*9+t];
    float bb = bdw[c];
    float* dst = g_f2 + ((long long)b*CC + c)*HW;
    for (int i = tid; i < 1024; i += 256){
        int p = i << 2, h = p >> 6, w0 = p & 63;
        float ov[4];
#pragma unroll
        for (int q2 = 0; q2 < 4; q2++){
            int w = w0 + q2;
            float s = bb;
#pragma unroll
            for (int ky = 0; ky < 3; ky++){
                int hh = h + ky - 1;
                if ((unsigned)hh > 63u) continue;
#pragma unroll
                for (int kx = 0; kx < 3; kx++){
                    int ww = w + kx - 1;
                    if ((unsigned)ww > 63u) continue;
                    s = fmaf(w9[ky*3+kx], sm[hh][ww], s);
                }
            }
            ov[q2] = s;
        }
        *(float4*)(dst + p) = make_float4(ov[0], ov[1], ov[2], ov[3]);
    }
}

// ---------------- host launcher ----------------
extern "C" void kernel_launch(void* const* d_in, const int* in_sizes, int n_in,
                              void* d_out, int out_size)
{
    const float* x         = (const float*)d_in[0];
    const float* qp_w      = (const float*)d_in[1];
    const float* qp_b      = (const float*)d_in[2];
    const float* mem_keys  = (const float*)d_in[3];
    const float* mem_values= (const float*)d_in[4];
    const float* vd_w1     = (const float*)d_in[5];
    const float* vd_b1     = (const float*)d_in[6];
    const float* vd_wdw    = (const float*)d_in[7];
    const float* vd_bdw    = (const float*)d_in[8];
    const float* fn_w1     = (const float*)d_in[9];
    const float* fn_b1     = (const float*)d_in[10];
    const float* fn_gamma  = (const float*)d_in[11];
    const float* fn_beta   = (const float*)d_in[12];
    const float* fn_wdw    = (const float*)d_in[13];
    const float* fn_bdw    = (const float*)d_in[14];
    const float* fn_w2     = (const float*)d_in[15];
    const float* fn_b2     = (const float*)d_in[16];
    const float* fg_w      = (const float*)d_in[17];
    const float* fg_b      = (const float*)d_in[18];
    float* out = (float*)d_out;
    (void)in_sizes; (void)n_in; (void)out_size;

    float *p_t, *p_big, *p_f2, *p_qp;
    __nv_bfloat16 *p_whi, *p_wlo, *p_w2hi, *p_w2lo, *p_qphi, *p_qplo,
                  *p_bthi, *p_btlo, *p_fthi, *p_ftlo;
    cudaGetSymbolAddress((void**)&p_t,    g_t);
    cudaGetSymbolAddress((void**)&p_big,  g_big);
    cudaGetSymbolAddress((void**)&p_f2,   g_f2);
    cudaGetSymbolAddress((void**)&p_qp,   g_qp);
    cudaGetSymbolAddress((void**)&p_whi,  g_whi);
    cudaGetSymbolAddress((void**)&p_wlo,  g_wlo);
    cudaGetSymbolAddress((void**)&p_w2hi, g_w2hi);
    cudaGetSymbolAddress((void**)&p_w2lo, g_w2lo);
    cudaGetSymbolAddress((void**)&p_qphi, g_qphi);
    cudaGetSymbolAddress((void**)&p_qplo, g_qplo);
    cudaGetSymbolAddress((void**)&p_bthi, g_bthi);
    cudaGetSymbolAddress((void**)&p_btlo, g_btlo);
    cudaGetSymbolAddress((void**)&p_fthi, g_fthi);
    cudaGetSymbolAddress((void**)&p_ftlo, g_ftlo);

    const int DSM = 2 * STAGE_B;   // 81920
    cudaFuncSetAttribute(gemm_tc<0>, cudaFuncAttributeMaxDynamicSharedMemorySize, DSM);
    cudaFuncSetAttribute(gemm_tc<1>, cudaFuncAttributeMaxDynamicSharedMemorySize, DSM);
    cudaFuncSetAttribute(gemm_tc<2>, cudaFuncAttributeMaxDynamicSharedMemorySize, DSM);

    const long long sX = (long long)CC*HW;

    // 0) weight conversions (bf16 split)
    convsplit<<<(CC*2*CC+255)/256,256>>>(p_whi,            p_wlo,            fn_w1, CC*2*CC);
    convsplit<<<(CC*2*CC+255)/256,256>>>(p_whi + CC*2*CC,  p_wlo + CC*2*CC,  fg_w,  CC*2*CC);
    convsplit<<<(CC*CC+255)/256,256>>>(p_w2hi, p_w2lo, fn_w2, CC*CC);
    qpsplit<<<(256*CC+255)/256,256>>>(p_qphi, p_qplo, qp_w);

    // 1) t[m] = vd_w1 @ mem_values[m] + vd_b1 (at 8x8 resolution)
    gemm_tpl<64,64><<<dim3(1,10,MR),256>>>(
        vd_w1, CC,
        mem_values, (long long)CC*64,
        vd_b1,
        p_t, (long long)CC*64,
        CC, 64, CC);

    // 2) x transposed + bf16 split (bt cols 0..639) — needed by qp GEMM and fn1 GEMM
    tsplit<<<dim3(HW/32, CC/32, BB),256>>>(x, sX, p_bthi, p_btlo, 2*CC, 0);

    // 3) q projection on tensor cores: gelu(qp_w@x + b), pixel-reduced partials
    gemm_tc<2><<<dim3(QT,2,BB),256,DSM>>>(
        p_qphi, p_qplo, CC,
        p_bthi, p_btlo, 2*CC,
        qp_b, qp_b, KDIM,
        nullptr, 0, CC,
        nullptr, 0, nullptr, 0, p_qp);

    // 4) cosine attention, top-2, softmax
    attn_kernel<<<1,256>>>(mem_keys);

    // 5) upsample + gelu + depthwise per memory row
    up_gelu_dw<<<MR*CC,256>>>(vd_wdw, vd_bdw);

    // 6) weighted reference -> bt cols 640..1279
    wtsplit<<<dim3(HW/32, CC/32, BB),256>>>(p_bthi, p_btlo);

    // 7) fused fn1 + gate GEMM (mma.sync bf16 split)
    gemm_tc<0><<<dim3(32,10,BB),256,DSM>>>(
        p_whi, p_wlo, 2*CC,
        p_bthi, p_btlo, 2*CC,
        fn_b1, fg_b, CC,
        p_big, (long long)2*CC*HW, 2*CC,
        nullptr, 0, nullptr, 0, nullptr);

    // 8) group-norm stats
    gn_stats<<<BB*GROUPS,256>>>();

    // 9) gn + gelu + depthwise
    gn_gelu_dw<<<BB*CC,256>>>(fn_gamma, fn_beta, fn_wdw, fn_bdw);

    // 10) f2 transpose + split
    tsplit<<<dim3(HW/32, CC/32, BB),256>>>(p_f2, sX, p_fthi, p_ftlo, CC, 0);

    // 11) fn2 GEMM + sigmoid-gate blend (mma.sync bf16 split)
    gemm_tc<1><<<dim3(32,5,BB),256,DSM>>>(
        p_w2hi, p_w2lo, CC,
        p_fthi, p_ftlo, CC,
        fn_b2, fn_b2, CC,
        out, (long long)CC*HW, CC,
        p_big + (long long)CC*HW, (long long)2*CC*HW,
        x, sX, nullptr);
}

// round 6
// speedup vs baseline: 2.2812x; 1.1103x over previous
#include <cuda_runtime.h>
#include <cuda_bf16.h>
#include <math.h>
#include <stdint.h>

// ---------------- problem constants ----------------
#define BB 8
#define CC 640
#define HW 4096     // 64*64
#define KDIM 160
#define MR 4
#define GROUPS 32
#define CPG 20      // 640/32
#define QT 32       // qp partial tiles

// ---------------- scratch (device globals; no allocs allowed) ----------------
__device__ float g_t   [MR*CC*64];
__device__ float g_dec [MR*CC*HW];
__device__ float g_big [BB*2*CC*HW];        // rows 0..639: f1 ; 640..1279: gate-pre
__device__ float g_qp  [BB*KDIM*QT];
__device__ float g_gn  [BB*GROUPS*2];
__device__ float g_attnw[BB*2];
__device__ int   g_attni[BB*2];

// bf16 split operands (all [*,k] for A / [k][p] channel-major planes for B)
__device__ __nv_bfloat16 g_whi [2*CC*2*CC];
__device__ __nv_bfloat16 g_wlo [2*CC*2*CC];
__device__ __nv_bfloat16 g_w2hi[CC*CC];
__device__ __nv_bfloat16 g_w2lo[CC*CC];
__device__ __nv_bfloat16 g_qphi[256*CC];     // qp_w zero-padded to 256 rows
__device__ __nv_bfloat16 g_qplo[256*CC];
__device__ __nv_bfloat16 g_xh [(long long)BB*CC*HW];   // x hi   [b][c][p]
__device__ __nv_bfloat16 g_xl [(long long)BB*CC*HW];   // x lo
__device__ __nv_bfloat16 g_wrh[(long long)BB*CC*HW];   // weighted-ref hi
__device__ __nv_bfloat16 g_wrl[(long long)BB*CC*HW];
__device__ __nv_bfloat16 g_f2h[(long long)BB*CC*HW];   // f2 hi
__device__ __nv_bfloat16 g_f2l[(long long)BB*CC*HW];

__device__ __forceinline__ float gelu_f(float v){
    return 0.5f*v*(1.0f + erff(v*0.70710678118654752f));
}

// ================= mma.sync helpers (sm_80+ base ISA) =================
__device__ __forceinline__ uint32_t smem_u32(const void* p){
    uint32_t a;
    asm("{ .reg .u64 t; cvta.to.shared.u64 t, %1; cvt.u32.u64 %0, t; }" : "=r"(a) : "l"(p));
    return a;
}
__device__ __forceinline__ void cpa16(uint32_t dst, const void* src){
    asm volatile("cp.async.cg.shared.global [%0], [%1], 16;" :: "r"(dst), "l"(src));
}
__device__ __forceinline__ void ldm_x4(uint32_t (&r)[4], uint32_t addr){
    asm volatile("ldmatrix.sync.aligned.m8n8.x4.shared.b16 {%0,%1,%2,%3}, [%4];"
        : "=r"(r[0]),"=r"(r[1]),"=r"(r[2]),"=r"(r[3]) : "r"(addr));
}
__device__ __forceinline__ void ldm_x2t(uint32_t (&r)[2], uint32_t addr){
    asm volatile("ldmatrix.sync.aligned.m8n8.x2.trans.shared.b16 {%0,%1}, [%2];"
        : "=r"(r[0]),"=r"(r[1]) : "r"(addr));
}
__device__ __forceinline__ void mma_bf16(float (&d)[4], const uint32_t (&a)[4], const uint32_t (&b)[2]){
    asm volatile("mma.sync.aligned.m16n8k16.row.col.f32.bf16.bf16.f32 "
        "{%0,%1,%2,%3}, {%4,%5,%6,%7}, {%8,%9}, {%0,%1,%2,%3};"
        : "+f"(d[0]),"+f"(d[1]),"+f"(d[2]),"+f"(d[3])
        : "r"(a[0]),"r"(a[1]),"r"(a[2]),"r"(a[3]), "r"(b[0]),"r"(b[1]));
}
__device__ __forceinline__ void split_bf16(float v, __nv_bfloat16& h, __nv_bfloat16& l){
    h = __float2bfloat16(v);
    l = __float2bfloat16(v - __bfloat162float(h));
}

// ================= split-bf16 tensor-core GEMM (mma.sync, trans-B) =================
// Y[bz, o, p] = sum_k W[o,k] * B[k, p] (+bias); B sourced from channel-major planes:
// rows k < splitB from plane1, else plane2 (both [bz][c][p]).
// CTA tile 128(M) x 128(N pixels), K-chunks of 32, 2-stage cp.async pipeline.
// EPI 0: plain store; 1: sigmoid-gate blend; 2: gelu + pixel-reduce (q projection).
#define KC 32
#define APITCH 80                 // A tile row pitch (64 data + 16 pad)
#define A_TILE (128*APITCH)       // 10240
#define BPITCH 272                // B tile row pitch (256 data + 16 pad)
#define B_TILE (KC*BPITCH)        // 8704
#define STAGE_B (2*A_TILE + 2*B_TILE)  // 37888

template<int EPI>
__global__ void __launch_bounds__(256,2) gemm_tc(
    const __nv_bfloat16* __restrict__ Whi, const __nv_bfloat16* __restrict__ Wlo,
    long long sA,
    const __nv_bfloat16* __restrict__ B1hi, const __nv_bfloat16* __restrict__ B1lo,
    const __nv_bfloat16* __restrict__ B2hi, const __nv_bfloat16* __restrict__ B2lo,
    int splitB,
    const float* __restrict__ biasa, const float* __restrict__ biasb, int rowSplit,
    float* __restrict__ Y, long long sY, int Kiter,
    const float* __restrict__ ep_g, long long s_g,
    const float* __restrict__ ep_x, long long s_x,
    float* __restrict__ ep_qp)
{
    extern __shared__ char smem[];
    const uint32_t sb = smem_u32(smem);
    const int tid = threadIdx.x, wid = tid >> 5, lane = tid & 31;
    const int warpM = wid >> 2, warpN = wid & 3;
    const int pBase = blockIdx.x * 128, oBase = blockIdx.y * 128, bz = blockIdx.z;
    const long long P = 4096;
    const long long sBpl = (long long)CC * HW;

    const __nv_bfloat16* ah_g = Whi + (long long)oBase * sA;
    const __nv_bfloat16* al_g = Wlo + (long long)oBase * sA;
    const __nv_bfloat16* b1h_p = B1hi + (long long)bz * sBpl + pBase;
    const __nv_bfloat16* b1l_p = B1lo + (long long)bz * sBpl + pBase;
    const __nv_bfloat16* b2h_p = B2hi + (long long)bz * sBpl + pBase;
    const __nv_bfloat16* b2l_p = B2lo + (long long)bz * sBpl + pBase;

    float acc[4][4][4];
#pragma unroll
    for (int a = 0; a < 4; a++)
#pragma unroll
        for (int b = 0; b < 4; b++)
#pragma unroll
            for (int c = 0; c < 4; c++) acc[a][b][c] = 0.f;

    // A ldmatrix per-thread offset (non-trans, [m][k] tiles, proven path)
    const uint32_t aoff = (uint32_t)((warpM*64 + (lane & 15)) * APITCH + (lane >> 4) * 16);
    // B trans-ldmatrix: lane l (0..15) addresses k-row (k0 + l), byte col = n0*2
    const uint32_t boff = (uint32_t)((lane & 15) * BPITCH + warpN * 64);

    const int nCh = Kiter / KC;

    auto load_stage = [&](int st, int c0){
        uint32_t base = sb + st * STAGE_B;
#pragma unroll
        for (int i = 0; i < 8; i++){
            int t = tid + (i << 8);
            if (t < 1024){
                // A tiles: 2 x 128 rows x 4 chunks
                int tile = t >> 9, u = t & 511, r = u >> 2, ck = u & 3;
                uint32_t dst = base + tile*A_TILE + (uint32_t)(r*APITCH + ck*16);
                const __nv_bfloat16* g = (tile ? al_g : ah_g);
                cpa16(dst, g + (long long)r * sA + c0 + (ck << 3));
            } else {
                // B tiles: 2 x 32 k-rows x 16 chunks, [k][p] layout
                int u2 = t - 1024;
                int tile = u2 >> 9, v = u2 & 511, r = v >> 4, ck = v & 15;
                uint32_t dst = base + 2*A_TILE + tile*B_TILE + (uint32_t)(r*BPITCH + ck*16);
                int krow = c0 + r;
                const __nv_bfloat16* src;
                if (krow < splitB)
                    src = (tile ? b1l_p : b1h_p) + (long long)krow * P + (ck << 3);
                else
                    src = (tile ? b2l_p : b2h_p) + (long long)(krow - splitB) * P + (ck << 3);
                cpa16(dst, src);
            }
        }
        asm volatile("cp.async.commit_group;" ::: "memory");
    };

    load_stage(0, 0);

    for (int ch = 0; ch < nCh; ch++){
        if (ch + 1 < nCh){
            load_stage((ch + 1) & 1, (ch + 1) * KC);
            asm volatile("cp.async.wait_group 1;" ::: "memory");
        } else {
            asm volatile("cp.async.wait_group 0;" ::: "memory");
        }
        __syncthreads();

        uint32_t base = sb + (ch & 1) * STAGE_B;
        uint32_t SAH = base, SAL = base + A_TILE;
        uint32_t SBH = base + 2*A_TILE, SBL = SBH + B_TILE;
#pragma unroll
        for (int ks = 0; ks < 2; ks++){
            uint32_t ako = ks * 32;              // 16 bf16 = 32 B along A row
            uint32_t bko = ks * 16 * BPITCH;     // 16 k-rows down B tile
            uint32_t bfr[4][2];
#pragma unroll
            for (int ni = 0; ni < 4; ni++)
                ldm_x2t(bfr[ni], SBH + boff + bko + ni*16);
            // hi*bh and lo*bh
#pragma unroll
            for (int mi = 0; mi < 4; mi++){
                uint32_t a[4];
                ldm_x4(a, SAH + aoff + mi*16*APITCH + ako);
#pragma unroll
                for (int ni = 0; ni < 4; ni++) mma_bf16(acc[mi][ni], a, bfr[ni]);
            }
#pragma unroll
            for (int mi = 0; mi < 4; mi++){
                uint32_t a[4];
                ldm_x4(a, SAL + aoff + mi*16*APITCH + ako);
#pragma unroll
                for (int ni = 0; ni < 4; ni++) mma_bf16(acc[mi][ni], a, bfr[ni]);
            }
            // hi*bl
#pragma unroll
            for (int ni = 0; ni < 4; ni++)
                ldm_x2t(bfr[ni], SBL + boff + bko + ni*16);
#pragma unroll
            for (int mi = 0; mi < 4; mi++){
                uint32_t a[4];
                ldm_x4(a, SAH + aoff + mi*16*APITCH + ako);
#pragma unroll
                for (int ni = 0; ni < 4; ni++) mma_bf16(acc[mi][ni], a, bfr[ni]);
            }
        }
        __syncthreads();
    }

    // ---- epilogue: acc -> SMEM stage (pitch 132) -> coalesced out ----
    float* stage = (float*)smem;
#pragma unroll
    for (int mi = 0; mi < 4; mi++){
        int r0 = warpM*64 + mi*16 + (lane >> 2);
#pragma unroll
        for (int ni = 0; ni < 4; ni++){
            int col = warpN*32 + ni*8 + 2*(lane & 3);
            stage[r0*132 + col]       = acc[mi][ni][0];
            stage[r0*132 + col + 1]   = acc[mi][ni][1];
            stage[(r0+8)*132 + col]   = acc[mi][ni][2];
            stage[(r0+8)*132 + col+1] = acc[mi][ni][3];
        }
    }
    __syncthreads();

    if (EPI == 2){
        // q projection: per-row gelu(v + bias) summed over 128 pixels
        int r = tid >> 1, h = tid & 1;
        int o = oBase + r;
        float s = 0.f;
        if (o < KDIM){
            float bo = biasa[o];
            const float* row = stage + r * 132 + h * 64;
#pragma unroll 8
            for (int j = 0; j < 64; j++) s += gelu_f(row[j] + bo);
        }
        s += __shfl_xor_sync(0xffffffffu, s, 1);
        if (h == 0 && o < KDIM)
            ep_qp[((bz*KDIM) + o)*QT + blockIdx.x] = s;
        return;
    }

    for (int i = tid; i < 128 * 128; i += 256){
        int r = i >> 7, c = i & 127;
        float v = stage[r * 132 + c];
        int o = oBase + r; long long p = pBase + c;
        float bo = (o < rowSplit) ? biasa[o] : biasb[o - rowSplit];
        v += bo;
        long long off = (long long)bz * sY + (long long)o * P + p;
        if (EPI == 1){
            float gp = ep_g[(long long)bz * s_g + (long long)o * P + p];
            float xr = ep_x[(long long)bz * s_x + (long long)o * P + p];
            float g = 1.0f / (1.0f + expf(-gp));
            v = g * v + (1.0f - g) * xr;
        }
        Y[off] = v;
    }
}

// ================= split helpers (all coalesced, no transpose) =================
__global__ void convsplit(__nv_bfloat16* __restrict__ hi, __nv_bfloat16* __restrict__ lo,
                          const float* __restrict__ src, int n){
    int i = blockIdx.x * 256 + threadIdx.x;
    if (i < n) split_bf16(src[i], hi[i], lo[i]);
}

__global__ void qpsplit(__nv_bfloat16* __restrict__ hi, __nv_bfloat16* __restrict__ lo,
                        const float* __restrict__ w){
    int i = blockIdx.x * 256 + threadIdx.x;
    if (i < 256*CC){
        float v = (i < KDIM*CC) ? w[i] : 0.f;
        split_bf16(v, hi[i], lo[i]);
    }
}

// x [b][c][p] fp32 -> xh/xl planes (same layout)
__global__ void xsplit(const float* __restrict__ src,
                       __nv_bfloat16* __restrict__ hi, __nv_bfloat16* __restrict__ lo){
    long long i4 = (long long)blockIdx.x * 256 + threadIdx.x;
    float4 v = ((const float4*)src)[i4];
    __nv_bfloat16 h0,h1,h2,h3,l0,l1,l2,l3;
    split_bf16(v.x,h0,l0); split_bf16(v.y,h1,l1);
    split_bf16(v.z,h2,l2); split_bf16(v.w,h3,l3);
    __nv_bfloat162* H = (__nv_bfloat162*)(hi + (i4<<2));
    __nv_bfloat162* L = (__nv_bfloat162*)(lo + (i4<<2));
    H[0] = __nv_bfloat162{h0,h1}; H[1] = __nv_bfloat162{h2,h3};
    L[0] = __nv_bfloat162{l0,l1}; L[1] = __nv_bfloat162{l2,l3};
}

// weighted reference blend -> wrh/wrl planes [b][c][p]
__global__ void wblend(__nv_bfloat16* __restrict__ hi, __nv_bfloat16* __restrict__ lo){
    long long i4 = (long long)blockIdx.x * 256 + threadIdx.x;
    long long e = i4 << 2;
    int b = (int)(e / ((long long)CC*HW));
    long long r = e - (long long)b*CC*HW;
    float a0 = g_attnw[b*2], a1 = g_attnw[b*2+1];
    const float4 d0 = *(const float4*)(g_dec + (long long)g_attni[b*2]  *CC*HW + r);
    const float4 d1 = *(const float4*)(g_dec + (long long)g_attni[b*2+1]*CC*HW + r);
    float4 v;
    v.x = a0*d0.x + a1*d1.x; v.y = a0*d0.y + a1*d1.y;
    v.z = a0*d0.z + a1*d1.z; v.w = a0*d0.w + a1*d1.w;
    __nv_bfloat16 h0,h1,h2,h3,l0,l1,l2,l3;
    split_bf16(v.x,h0,l0); split_bf16(v.y,h1,l1);
    split_bf16(v.z,h2,l2); split_bf16(v.w,h3,l3);
    __nv_bfloat162* H = (__nv_bfloat162*)(hi + e);
    __nv_bfloat162* L = (__nv_bfloat162*)(lo + e);
    H[0] = __nv_bfloat162{h0,h1}; H[1] = __nv_bfloat162{h2,h3};
    L[0] = __nv_bfloat162{l0,l1}; L[1] = __nv_bfloat162{l2,l3};
}

// ---------------- generic tiled SGEMM (small vd GEMM) ----------------
constexpr int GK = 16;

template<int TBM, int TBN>
__global__ __launch_bounds__(256) void gemm_tpl(
    const float* __restrict__ Wa,
    const float* __restrict__ Xa, long long sXa,
    const float* __restrict__ biasa,
    float* __restrict__ Y, long long sY,
    int M, int N, int K)
{
    constexpr int TM = TBM/16, TN = TBN/16;
    __shared__ float As[GK][TBM];
    __shared__ float Bs[GK][TBN];

    const int tid = threadIdx.x;
    const int tx = tid & 15, ty = tid >> 4;
    const int pBase = blockIdx.x * TBN;
    const int oBase = blockIdx.y * TBM;
    const int bz = blockIdx.z;

    float acc[TM][TN];
#pragma unroll
    for (int i = 0; i < TM; i++)
#pragma unroll
        for (int j = 0; j < TN; j++) acc[i][j] = 0.f;

    for (int c0 = 0; c0 < K; c0 += GK){
#pragma unroll
        for (int l = 0; l < TBM/64; l++){
            int i = (tid >> 2) + l*64;
            int j4 = (tid & 3) << 2;
            int o = oBase + i;
            float4 w = make_float4(0.f,0.f,0.f,0.f);
            if (o < M) w = *(const float4*)(Wa + (long long)o*K + c0 + j4);
            As[j4+0][i] = w.x; As[j4+1][i] = w.y; As[j4+2][i] = w.z; As[j4+3][i] = w.w;
        }
#pragma unroll
        for (int l = 0; l < TBN/64; l++){
            int j = tid >> 4;
            int n4 = ((tid & 15) << 2) + l*64;
            int c = c0 + j;
            const float* xp = Xa + bz*sXa + (long long)c*N;
            *(float4*)&Bs[j][n4] = *(const float4*)(xp + pBase + n4);
        }
        __syncthreads();
#pragma unroll
        for (int kk = 0; kk < GK; kk++){
            float a[TM], b[TN];
#pragma unroll
            for (int i = 0; i < TM; i += 4){
                float4 t = *(const float4*)&As[kk][ty*TM + i];
                a[i]=t.x; a[i+1]=t.y; a[i+2]=t.z; a[i+3]=t.w;
            }
#pragma unroll
            for (int j = 0; j < TN; j += 4){
                float4 t = *(const float4*)&Bs[kk][tx*TN + j];
                b[j]=t.x; b[j+1]=t.y; b[j+2]=t.z; b[j+3]=t.w;
            }
#pragma unroll
            for (int i = 0; i < TM; i++)
#pragma unroll
                for (int j = 0; j < TN; j++)
                    acc[i][j] = fmaf(a[i], b[j], acc[i][j]);
        }
        __syncthreads();
    }

#pragma unroll
    for (int i = 0; i < TM; i++){
        int o = oBase + ty*TM + i;
        if (o >= M) continue;
        float bo = biasa[o];
#pragma unroll
        for (int j = 0; j < TN; j += 4){
            float4 r = make_float4(acc[i][j]+bo, acc[i][j+1]+bo,
                                   acc[i][j+2]+bo, acc[i][j+3]+bo);
            *(float4*)(Y + bz*sY + (long long)o*N + pBase + tx*TN + j) = r;
        }
    }
}

// ---------------- attention: q reduce, cosine sims, top-2, softmax ----------------
__global__ void attn_kernel(const float* __restrict__ mem_keys){
    __shared__ float qs[BB*KDIM];
    int tid = threadIdx.x;
    for (int idx = tid; idx < BB*KDIM; idx += 256){
        const float* p = g_qp + (long long)idx*QT;
        float s = 0.f;
        for (int t = 0; t < QT; t++) s += p[t];
        qs[idx] = s * (1.0f/4096.0f);
    }
    __syncthreads();
    if (tid < BB){
        int b = tid;
        const float* q = qs + b*KDIM;
        float qn = 0.f;
        for (int j = 0; j < KDIM; j++) qn += q[j]*q[j];
        qn = fmaxf(sqrtf(qn), 1e-12f);
        float v[MR];
        for (int m = 0; m < MR; m++){
            const float* kk = mem_keys + m*KDIM;
            float kn = 0.f, d = 0.f;
            for (int j = 0; j < KDIM; j++){ kn += kk[j]*kk[j]; d += q[j]*kk[j]; }
            kn = fmaxf(sqrtf(kn), 1e-12f);
            v[m] = d/(qn*kn);
        }
        int i0 = 0;
        for (int m = 1; m < MR; m++) if (v[m] > v[i0]) i0 = m;
        int i1 = -1;
        for (int m = 0; m < MR; m++){
            if (m == i0) continue;
            if (i1 < 0 || v[m] > v[i1]) i1 = m;
        }
        float e1 = expf((v[i1]-v[i0])*10.0f);
        float a0 = 1.0f/(1.0f+e1);
        float a1 = e1/(1.0f+e1);
        g_attnw[b*2] = a0; g_attnw[b*2+1] = a1;
        g_attni[b*2] = i0; g_attni[b*2+1] = i1;
    }
}

// ---------------- bilinear 8->64 upsample + gelu + depthwise 3x3 ----------------
__global__ __launch_bounds__(256) void up_gelu_dw(
    const float* __restrict__ wdw, const float* __restrict__ bdw)
{
    int m = blockIdx.x / CC, c = blockIdx.x % CC;
    __shared__ float sm[64][65];
    __shared__ float tt[64];
    int tid = threadIdx.x;
    if (tid < 64) tt[tid] = g_t[((long long)m*CC + c)*64 + tid];
    __syncthreads();
    for (int i = tid; i < 1024; i += 256){
        int p = i << 2, h = p >> 6, w0 = p & 63;
        float shf = h*0.125f - 0.4375f;
        int ih = (int)floorf(shf);
        float fh = shf - (float)ih;
        int h0 = ih < 0 ? 0 : ih;
        int h1 = (ih+1 > 7) ? 7 : ih+1;
#pragma unroll
        for (int q2 = 0; q2 < 4; q2++){
            int w = w0 + q2;
            float swf = w*0.125f - 0.4375f;
            int iw = (int)floorf(swf);
            float fw = swf - (float)iw;
            int wA = iw < 0 ? 0 : iw;
            int wB = (iw+1 > 7) ? 7 : iw+1;
            float top = (1.f-fw)*tt[h0*8+wA] + fw*tt[h0*8+wB];
            float bot = (1.f-fw)*tt[h1*8+wA] + fw*tt[h1*8+wB];
            float v = (1.f-fh)*top + fh*bot;
            sm[h][w] = gelu_f(v);
        }
    }
    __syncthreads();
    float w9[9];
#pragma unroll
    for (int t = 0; t < 9; t++) w9[t] = wdw[c*9+t];
    float bb = bdw[c];
    float* dst = g_dec + ((long long)m*CC + c)*HW;
    for (int i = tid; i < 1024; i += 256){
        int p = i << 2, h = p >> 6, w0 = p & 63;
        float ov[4];
#pragma unroll
        for (int q2 = 0; q2 < 4; q2++){
            int w = w0 + q2;
            float s = bb;
#pragma unroll
            for (int ky = 0; ky < 3; ky++){
                int hh = h + ky - 1;
                if ((unsigned)hh > 63u) continue;
#pragma unroll
                for (int kx = 0; kx < 3; kx++){
                    int ww = w + kx - 1;
                    if ((unsigned)ww > 63u) continue;
                    s = fmaf(w9[ky*3+kx], sm[hh][ww], s);
                }
            }
            ov[q2] = s;
        }
        *(float4*)(dst + p) = make_float4(ov[0], ov[1], ov[2], ov[3]);
    }
}

// ---------------- group-norm statistics ----------------
__global__ void gn_stats(){
    int b = blockIdx.x >> 5, g = blockIdx.x & 31;
    int tid = threadIdx.x;
    const float4* p = (const float4*)(g_big + ((long long)b*2*CC + g*CPG)*HW);
    const int n4 = CPG*HW/4;
    float s = 0.f, ss = 0.f;
    for (int i = tid; i < n4; i += 256){
        float4 v = p[i];
        s  += v.x + v.y + v.z + v.w;
        ss += v.x*v.x + v.y*v.y + v.z*v.z + v.w*v.w;
    }
    __shared__ float sh1[256], sh2[256];
    sh1[tid] = s; sh2[tid] = ss;
    __syncthreads();
    for (int st = 128; st > 0; st >>= 1){
        if (tid < st){ sh1[tid] += sh1[tid+st]; sh2[tid] += sh2[tid+st]; }
        __syncthreads();
    }
    if (tid == 0){
        const float inv = 1.0f/(CPG*HW);
        float mu = sh1[0]*inv;
        float var = sh2[0]*inv - mu*mu;
        g_gn[blockIdx.x*2]   = mu;
        g_gn[blockIdx.x*2+1] = rsqrtf(var + 1e-5f);
    }
}

// ---------------- group-norm + gelu + depthwise 3x3 -> bf16 split planes ----------------
__global__ __launch_bounds__(256) void gn_gelu_dw(
    const float* __restrict__ gamma, const float* __restrict__ beta,
    const float* __restrict__ wdw, const float* __restrict__ bdw)
{
    int b = blockIdx.x / CC, c = blockIdx.x % CC;
    __shared__ float sm[64][65];
    int tid = threadIdx.x;
    const float* src = g_big + ((long long)b*2*CC + c)*HW;
    int g = c / CPG;
    float mu = g_gn[(b*GROUPS+g)*2], rs = g_gn[(b*GROUPS+g)*2+1];
    float ga = gamma[c]*rs;
    float be = beta[c] - mu*ga;
    for (int i = tid; i < 1024; i += 256){
        float4 v = ((const float4*)src)[i];
        int p = i << 2, h = p >> 6, w0 = p & 63;
        sm[h][w0]   = gelu_f(v.x*ga + be);
        sm[h][w0+1] = gelu_f(v.y*ga + be);
        sm[h][w0+2] = gelu_f(v.z*ga + be);
        sm[h][w0+3] = gelu_f(v.w*ga + be);
    }
    __syncthreads();
    float w9[9];
#pragma unroll
    for (int t = 0; t < 9; t++) w9[t] = wdw[c*9+t];
    float bb = bdw[c];
    __nv_bfloat16* dh = g_f2h + ((long long)b*CC + c)*HW;
    __nv_bfloat16* dl = g_f2l + ((long long)b*CC + c)*HW;
    for (int i = tid; i < 1024; i += 256){
        int p = i << 2, h = p >> 6, w0 = p & 63;
        float ov[4];
#pragma unroll
        for (int q2 = 0; q2 < 4; q2++){
            int w = w0 + q2;
            float s = bb;
#pragma unroll
            for (int ky = 0; ky < 3; ky++){
                int hh = h + ky - 1;
                if ((unsigned)hh > 63u) continue;
#pragma unroll
                for (int kx = 0; kx < 3; kx++){
                    int ww = w + kx - 1;
                    if ((unsigned)ww > 63u) continue;
                    s = fmaf(w9[ky*3+kx], sm[hh][ww], s);
                }
            }
            ov[q2] = s;
        }
        __nv_bfloat16 h0,h1,h2,h3,l0,l1,l2,l3;
        split_bf16(ov[0],h0,l0); split_bf16(ov[1],h1,l1);
        split_bf16(ov[2],h2,l2); split_bf16(ov[3],h3,l3);
        __nv_bfloat162* H = (__nv_bfloat162*)(dh + p);
        __nv_bfloat162* L = (__nv_bfloat162*)(dl + p);
        H[0] = __nv_bfloat162{h0,h1}; H[1] = __nv_bfloat162{h2,h3};
        L[0] = __nv_bfloat162{l0,l1}; L[1] = __nv_bfloat162{l2,l3};
    }
}

// ---------------- host launcher ----------------
extern "C" void kernel_launch(void* const* d_in, const int* in_sizes, int n_in,
                              void* d_out, int out_size)
{
    const float* x         = (const float*)d_in[0];
    const float* qp_w      = (const float*)d_in[1];
    const float* qp_b      = (const float*)d_in[2];
    const float* mem_keys  = (const float*)d_in[3];
    const float* mem_values= (const float*)d_in[4];
    const float* vd_w1     = (const float*)d_in[5];
    const float* vd_b1     = (const float*)d_in[6];
    const float* vd_wdw    = (const float*)d_in[7];
    const float* vd_bdw    = (const float*)d_in[8];
    const float* fn_w1     = (const float*)d_in[9];
    const float* fn_b1     = (const float*)d_in[10];
    const float* fn_gamma  = (const float*)d_in[11];
    const float* fn_beta   = (const float*)d_in[12];
    const float* fn_wdw    = (const float*)d_in[13];
    const float* fn_bdw    = (const float*)d_in[14];
    const float* fn_w2     = (const float*)d_in[15];
    const float* fn_b2     = (const float*)d_in[16];
    const float* fg_w      = (const float*)d_in[17];
    const float* fg_b      = (const float*)d_in[18];
    float* out = (float*)d_out;
    (void)in_sizes; (void)n_in; (void)out_size;

    float *p_t, *p_big, *p_qp;
    __nv_bfloat16 *p_whi, *p_wlo, *p_w2hi, *p_w2lo, *p_qphi, *p_qplo,
                  *p_xh, *p_xl, *p_wrh, *p_wrl, *p_f2h, *p_f2l;
    cudaGetSymbolAddress((void**)&p_t,    g_t);
    cudaGetSymbolAddress((void**)&p_big,  g_big);
    cudaGetSymbolAddress((void**)&p_qp,   g_qp);
    cudaGetSymbolAddress((void**)&p_whi,  g_whi);
    cudaGetSymbolAddress((void**)&p_wlo,  g_wlo);
    cudaGetSymbolAddress((void**)&p_w2hi, g_w2hi);
    cudaGetSymbolAddress((void**)&p_w2lo, g_w2lo);
    cudaGetSymbolAddress((void**)&p_qphi, g_qphi);
    cudaGetSymbolAddress((void**)&p_qplo, g_qplo);
    cudaGetSymbolAddress((void**)&p_xh,   g_xh);
    cudaGetSymbolAddress((void**)&p_xl,   g_xl);
    cudaGetSymbolAddress((void**)&p_wrh,  g_wrh);
    cudaGetSymbolAddress((void**)&p_wrl,  g_wrl);
    cudaGetSymbolAddress((void**)&p_f2h,  g_f2h);
    cudaGetSymbolAddress((void**)&p_f2l,  g_f2l);

    const int DSM = 2 * STAGE_B;   // 75776 (epilogue fp32 stage 67584 fits)
    cudaFuncSetAttribute(gemm_tc<0>, cudaFuncAttributeMaxDynamicSharedMemorySize, DSM);
    cudaFuncSetAttribute(gemm_tc<1>, cudaFuncAttributeMaxDynamicSharedMemorySize, DSM);
    cudaFuncSetAttribute(gemm_tc<2>, cudaFuncAttributeMaxDynamicSharedMemorySize, DSM);

    const long long sX = (long long)CC*HW;

    // 0) weight conversions (bf16 split)
    convsplit<<<(CC*2*CC+255)/256,256>>>(p_whi,            p_wlo,            fn_w1, CC*2*CC);
    convsplit<<<(CC*2*CC+255)/256,256>>>(p_whi + CC*2*CC,  p_wlo + CC*2*CC,  fg_w,  CC*2*CC);
    convsplit<<<(CC*CC+255)/256,256>>>(p_w2hi, p_w2lo, fn_w2, CC*CC);
    qpsplit<<<(256*CC+255)/256,256>>>(p_qphi, p_qplo, qp_w);

    // 1) x -> bf16 split planes (coalesced, no transpose)
    xsplit<<<(int)((long long)BB*CC*HW/4/256),256>>>(x, p_xh, p_xl);

    // 2) t[m] = vd_w1 @ mem_values[m] + vd_b1 (at 8x8 resolution)
    gemm_tpl<64,64><<<dim3(1,10,MR),256>>>(
        vd_w1, mem_values, (long long)CC*64, vd_b1,
        p_t, (long long)CC*64, CC, 64, CC);

    // 3) q projection (tensor cores): gelu(qp_w@x + b), pixel-reduced partials
    gemm_tc<2><<<dim3(QT,2,BB),256,DSM>>>(
        p_qphi, p_qplo, CC,
        p_xh, p_xl, p_xh, p_xl, CC,
        qp_b, qp_b, KDIM,
        nullptr, 0, CC,
        nullptr, 0, nullptr, 0, p_qp);

    // 4) cosine attention, top-2, softmax
    attn_kernel<<<1,256>>>(mem_keys);

    // 5) upsample + gelu + depthwise per memory row
    up_gelu_dw<<<MR*CC,256>>>(vd_wdw, vd_bdw);

    // 6) weighted reference blend -> bf16 split planes
    wblend<<<(int)((long long)BB*CC*HW/4/256),256>>>(p_wrh, p_wrl);

    // 7) fused fn1 + gate GEMM (trans-B from x/wref planes)
    gemm_tc<0><<<dim3(32,10,BB),256,DSM>>>(
        p_whi, p_wlo, 2*CC,
        p_xh, p_xl, p_wrh, p_wrl, CC,
        fn_b1, fg_b, CC,
        p_big, (long long)2*CC*HW, 2*CC,
        nullptr, 0, nullptr, 0, nullptr);

    // 8) group-norm stats
    gn_stats<<<BB*GROUPS,256>>>();

    // 9) gn + gelu + depthwise -> f2 bf16 split planes
    gn_gelu_dw<<<BB*CC,256>>>(fn_gamma, fn_beta, fn_wdw, fn_bdw);

    // 10) fn2 GEMM + sigmoid-gate blend (trans-B from f2 planes)
    gemm_tc<1><<<dim3(32,5,BB),256,DSM>>>(
        p_w2hi, p_w2lo, CC,
        p_f2h, p_f2l, p_f2h, p_f2l, CC,
        fn_b2, fn_b2, CC,
        out, (long long)CC*HW, CC,
        p_big + (long long)CC*HW, (long long)2*CC*HW,
        x, sX, nullptr);
}